// round 12
// baseline (speedup 1.0000x reference)
#include <cuda_runtime.h>
#include <cuda_fp16.h>
#include <cstdint>
#include <math.h>

typedef __half ht;

#define NCH  512
#define NSP  1024
#define NB   16
#define CHN  (NCH*NSP)
#define QS   0.08838834764831845f
#define QSE  (0.08838834764831845f * 1.4426950408889634f)   // fold log2(e) for exp2

// --------------------------- scratch (device globals) ------------------------
__device__ ht g_xn [(size_t)NB*NSP*NCH];      // [b][n][c]
__device__ ht g_wq [1536*512];
__device__ ht g_wp [512*512];
__device__ ht g_qk [(size_t)NB*NSP*1024];     // [b][n][q(512)|k(512)]
__device__ ht g_v  [(size_t)NB*NCH*NSP];      // [b][c][m]
__device__ ht g_oT [(size_t)NB*NSP*NCH];      // [b][n][c]

// ------------------------------ PTX helpers ----------------------------------
__device__ __forceinline__ uint32_t smem_u32(const void* p) {
    uint32_t a;
    asm("{ .reg .u64 t; cvta.to.shared.u64 t, %1; cvt.u32.u64 %0, t; }" : "=r"(a) : "l"(p));
    return a;
}
__device__ __forceinline__ void ldsm4(uint32_t* r, uint32_t addr) {
    asm volatile("ldmatrix.sync.aligned.m8n8.x4.shared.b16 {%0,%1,%2,%3}, [%4];"
        : "=r"(r[0]), "=r"(r[1]), "=r"(r[2]), "=r"(r[3]) : "r"(addr));
}
__device__ __forceinline__ void mma16816(float* d, const uint32_t* a, uint32_t b0, uint32_t b1) {
    asm volatile("mma.sync.aligned.m16n8k16.row.col.f32.f16.f16.f32 "
        "{%0,%1,%2,%3}, {%4,%5,%6,%7}, {%8,%9}, {%0,%1,%2,%3};"
        : "+f"(d[0]), "+f"(d[1]), "+f"(d[2]), "+f"(d[3])
        : "r"(a[0]), "r"(a[1]), "r"(a[2]), "r"(a[3]), "r"(b0), "r"(b1));
}
__device__ __forceinline__ void mma16816h(uint32_t* d, const uint32_t* a, uint32_t b0, uint32_t b1) {
    asm volatile("mma.sync.aligned.m16n8k16.row.col.f16.f16.f16.f16 "
        "{%0,%1}, {%2,%3,%4,%5}, {%6,%7}, {%0,%1};"
        : "+r"(d[0]), "+r"(d[1])
        : "r"(a[0]), "r"(a[1]), "r"(a[2]), "r"(a[3]), "r"(b0), "r"(b1));
}
__device__ __forceinline__ uint32_t pack2(float a, float b) {
    __half2 p = __floats2half2_rn(a, b);
    return *(uint32_t*)&p;
}
__device__ __forceinline__ uint32_t ex2h2(uint32_t x) {
    uint32_t y;
    asm("ex2.approx.f16x2 %0, %1;" : "=r"(y) : "r"(x));
    return y;
}
#define CP_ASYNC(dst, src) asm volatile("cp.async.cg.shared.global [%0], [%1], 16;" :: "r"(dst), "l"(src))
#define CP_COMMIT()  asm volatile("cp.async.commit_group;" ::: "memory")
#define CP_WAIT3()   asm volatile("cp.async.wait_group 3;" ::: "memory")
#define CP_WAIT1()   asm volatile("cp.async.wait_group 1;" ::: "memory")
#define CP_WAIT0()   asm volatile("cp.async.wait_group 0;" ::: "memory")

// --------------------------- weight convert ----------------------------------
__global__ __launch_bounds__(256)
void convw_kernel(const float* __restrict__ wq, const float* __restrict__ wp,
                  ht* __restrict__ wqo, ht* __restrict__ wpo) {
    int i = blockIdx.x * 256 + threadIdx.x;
    if (i < 1536*512) {
        float v = wq[i];
        if (i < 512*512) v *= QSE;                // fold (1/sqrt(hd))*log2(e) into w_q
        wqo[i] = __float2half_rn(v);
    } else {
        int j = i - 1536*512;
        if (j < 512*512) wpo[j] = __float2half_rn(wp[j]);
    }
}

// ------------------------------ GroupNorm ------------------------------------
__global__ __launch_bounds__(256)
void groupnorm_kernel(const float* __restrict__ x, const float* __restrict__ gamma,
                      const float* __restrict__ beta, ht* __restrict__ xn) {
    const int b = blockIdx.x >> 5, g = blockIdx.x & 31;
    const float* xp = x + (size_t)b * CHN + (size_t)g * (16 * NSP);

    float s = 0.f, s2 = 0.f;
    for (int i = threadIdx.x; i < 16 * NSP; i += 256) {
        float v = xp[i]; s += v; s2 += v * v;
    }
    __shared__ float rs[8], rs2[8];
    for (int o = 16; o; o >>= 1) {
        s  += __shfl_xor_sync(0xffffffffu, s,  o);
        s2 += __shfl_xor_sync(0xffffffffu, s2, o);
    }
    int wid = threadIdx.x >> 5;
    if ((threadIdx.x & 31) == 0) { rs[wid] = s; rs2[wid] = s2; }
    __syncthreads();
    s = 0.f; s2 = 0.f;
    #pragma unroll
    for (int i = 0; i < 8; i++) { s += rs[i]; s2 += rs2[i]; }
    const float inv = 1.0f / (16 * NSP);
    float mu = s * inv;
    float rstd = rsqrtf(s2 * inv - mu * mu + 1e-5f);

    const int gc = g * 16;
    for (int n = threadIdx.x; n < NSP; n += 256) {
        union { ht h[16]; uint4 u[2]; } H;
        #pragma unroll
        for (int c = 0; c < 16; ++c) {
            float v = (xp[c * NSP + n] - mu) * rstd * gamma[gc + c] + beta[gc + c];
            H.h[c] = __float2half_rn(v);
        }
        uint4* dh = (uint4*)(g_xn + (size_t)b * (NSP * NCH) + (size_t)n * NCH + gc);
        dh[0] = H.u[0]; dh[1] = H.u[1];
    }
}

// --------------------------- mma.sync GEMM v2 --------------------------------
// CTA tile 128(M) x 256(N), 8 warps as 2(M) x 4(N), warp tile 64x64.
// 4 MMAs per ldsm.x4 (vs 2.67 before) -> tensor-bound, not smem-bound.
// MODE 0: QKV  (z=b) M=1536 N=1024 K=512 : q/k -> qkT transposed, v -> [b][c][m]
// MODE 3: proj (z=b) M=512  N=1024 K=512 : fp32 out (+bias+x)
#define SROW   80
#define ATILE  10240       // 128 * 80
#define BTILE  20480       // 256 * 80
#define STAGE2 30720
#define NSTAGE 4
#define SMEMSZ (NSTAGE*STAGE2)   // 122880, 1 CTA/SM

template<int MODE>
__global__ __launch_bounds__(256, 1)
void gemm_mma(const ht* __restrict__ Ap, const ht* __restrict__ Bp,
              float* __restrict__ C,
              ht* __restrict__ Oh, ht* __restrict__ Vh,
              const float* __restrict__ bias, const float* __restrict__ resid) {
    extern __shared__ char smem[];
    const uint32_t sbase = smem_u32(smem);
    const int tid = threadIdx.x, lane = tid & 31, wid = tid >> 5;
    const int wm = wid >> 2, wn = wid & 3;       // 2 warps M, 4 warps N
    const int m_w = wm * 64, n_w = wn * 64;
    const int z = blockIdx.z, m0 = blockIdx.y * 128, n0 = blockIdx.x * 256;

    const int lda = 512, ldb = 512, Ktot = 512;
    const size_t aoff = (size_t)m0 * 512;
    const size_t boff = (size_t)z * (NSP * NCH) + (size_t)n0 * 512;

    float acc[4][8][4] = {};
    const int NIT = Ktot / 32;

    auto load_stage = [&](int it, int s) {
        const int k0 = it * 32;
        const uint32_t sb = sbase + s * STAGE2;
        #pragma unroll
        for (int i = 0; i < 6; ++i) {
            int c = tid + i * 256;
            if (i < 2) {                              // A: 512 chunks
                int row = c >> 2, col = c & 3;
                CP_ASYNC(sb + row * SROW + col * 16,
                         Ap + aoff + (size_t)row * lda + k0 + col * 8);
            } else {                                  // B: 1024 chunks
                int d = c - 512;
                int row = d >> 2, col = d & 3;
                CP_ASYNC(sb + ATILE + row * SROW + col * 16,
                         Bp + boff + (size_t)row * ldb + k0 + col * 8);
            }
        }
        CP_COMMIT();
    };

    #pragma unroll
    for (int p = 0; p < NSTAGE - 1; ++p)
        if (p < NIT) load_stage(p, p);

    for (int it = 0; it < NIT; ++it) {
        const int s = it & (NSTAGE - 1);
        if (it + NSTAGE - 1 < NIT) {
            load_stage(it + NSTAGE - 1, (it + NSTAGE - 1) & (NSTAGE - 1));
            CP_WAIT3();
        } else {
            CP_WAIT0();
        }
        __syncthreads();

        const uint32_t ab = sbase + s * STAGE2;
        const uint32_t rofs = (lane & 15) * SROW + ((lane >> 4) << 4);
        #pragma unroll
        for (int k16 = 0; k16 < 2; ++k16) {
            const uint32_t ko = k16 * 32 + rofs;
            uint32_t bfr[4][4];
            #pragma unroll
            for (int j = 0; j < 4; ++j)
                ldsm4(bfr[j], ab + ATILE + (n_w + j * 16) * SROW + ko);
            uint32_t af[4][4];
            #pragma unroll
            for (int i = 0; i < 4; ++i)
                ldsm4(af[i], ab + (m_w + i * 16) * SROW + ko);
            #pragma unroll
            for (int i = 0; i < 4; ++i)
                #pragma unroll
                for (int jn = 0; jn < 8; ++jn)
                    mma16816(acc[i][jn], af[i],
                             bfr[jn >> 1][jn & 1], bfr[jn >> 1][(jn & 1) + 2]);
        }
        __syncthreads();
    }

    const int fr = lane >> 2;
    const int fc = (lane & 3) * 2;

    if (MODE == 3) {
        #pragma unroll
        for (int i = 0; i < 4; ++i)
            #pragma unroll
            for (int jn = 0; jn < 8; ++jn)
                #pragma unroll
                for (int rh = 0; rh < 2; ++rh) {
                    int row = m0 + m_w + i * 16 + fr + rh * 8;
                    int col = n0 + n_w + jn * 8 + fc;
                    float bv = bias[row];
                    const float2 xv = *(const float2*)(resid + (size_t)z * CHN + (size_t)row * NSP + col);
                    *(float2*)(C + (size_t)z * CHN + (size_t)row * NSP + col) =
                        make_float2(acc[i][jn][rh * 2] + bv + xv.x,
                                    acc[i][jn][rh * 2 + 1] + bv + xv.y);
                }
    } else if (MODE == 0 && m0 >= 1024) {
        // V region: [b][c][m]
        #pragma unroll
        for (int i = 0; i < 4; ++i)
            #pragma unroll
            for (int jn = 0; jn < 8; ++jn)
                #pragma unroll
                for (int rh = 0; rh < 2; ++rh) {
                    int mi = m_w + i * 16 + fr + rh * 8;
                    float bv = bias[m0 + mi];
                    int cc2 = m0 - 1024 + mi;
                    size_t off = (size_t)z * (NCH * NSP) + (size_t)cc2 * NSP + n0 + n_w + jn * 8 + fc;
                    *(__half2*)(Vh + off) = __halves2half2(
                        __float2half_rn(acc[i][jn][rh * 2] + bv),
                        __float2half_rn(acc[i][jn][rh * 2 + 1] + bv));
                }
    } else {
        // q/k region -> transposed qkT; 4 n-quarters of 64
        uint32_t* TB = (uint32_t*)smem;       // [64 n][132 m]
        #pragma unroll
        for (int hh = 0; hh < 4; ++hh) {
            __syncthreads();
            if (wn == hh) {
                #pragma unroll
                for (int i = 0; i < 4; ++i)
                    #pragma unroll
                    for (int jn = 0; jn < 8; ++jn)
                        #pragma unroll
                        for (int rh = 0; rh < 2; ++rh) {
                            int mi = m_w + i * 16 + fr + rh * 8;
                            float bv = bias[m0 + mi];
                            if (m0 < 512) bv *= QSE;
                            float v0 = acc[i][jn][rh * 2] + bv;
                            float v1 = acc[i][jn][rh * 2 + 1] + bv;
                            int ncl = jn * 8 + fc;
                            TB[ncl * 132 + mi]       = (uint32_t)__half_as_ushort(__float2half_rn(v0));
                            TB[(ncl + 1) * 132 + mi] = (uint32_t)__half_as_ushort(__float2half_rn(v1));
                        }
            }
            __syncthreads();
            int rr = tid >> 2, seg = (tid & 3) * 32;
            size_t nco = (size_t)z * (NSP * 1024) + (size_t)(n0 + hh * 64 + rr) * 1024 + m0 + seg;
            #pragma unroll
            for (int q4 = 0; q4 < 4; ++q4) {
                union { ht h[8]; uint4 u; } H;
                #pragma unroll
                for (int e = 0; e < 8; ++e)
                    H.h[e] = __ushort_as_half((unsigned short)(TB[rr * 132 + seg + q4 * 8 + e] & 0xffffu));
                *(uint4*)(Oh + nco + q4 * 8) = H.u;
            }
        }
    }
}

// ------------------------- flash attention v5 --------------------------------
// 128 threads (4 warps), q-tile 128 (32 q rows/warp), kv-chunk 64, 2 CTAs/SM.
// O-MMA interleaved into the kb4 loop -> pa lives 8 regs at a time (de-spill).
#define KROW  272                  // 128 halfs + 16B pad
#define VROW  144                  // 64 halfs + 16B pad
#define QTILE (128*KROW)           // 34816
#define KTILE (64*KROW)            // 17408
#define VTILE (128*VROW)           // 18432
#define FSTG  (KTILE+VTILE)        // 35840
#define FSMEM (QTILE + 2*FSTG)     // 106496
#define ONESH2 0x3C003C00u

__global__ __launch_bounds__(128, 2)
void flash_kernel(const ht* __restrict__ QK, const ht* __restrict__ Vg_,
                  ht* __restrict__ O) {
    extern __shared__ char smem[];
    const uint32_t sbase = smem_u32(smem);
    const int tid = threadIdx.x, lane = tid & 31, wid = tid >> 5;
    const int z = blockIdx.y, b = z >> 2, h = z & 3;
    const int q0 = blockIdx.x * 128;

    const ht* Qg = QK  + (size_t)b * (NSP * 1024) + (size_t)q0 * 1024 + h * 128;
    const ht* Kg = QK  + (size_t)b * (NSP * 1024) + 512 + h * 128;
    const ht* Vg = Vg_ + (size_t)b * CHN + (size_t)(h * 128) * NSP;

    // Q tile: 128 rows x 128 halfs = 2048 16B chunks, 16/thread
    #pragma unroll
    for (int i = 0; i < 16; ++i) {
        int c = tid + i * 128;
        int row = c >> 4, col = c & 15;
        CP_ASYNC(sbase + row * KROW + col * 16, Qg + (size_t)row * 1024 + col * 8);
    }
    CP_COMMIT();

    auto load_kv = [&](int j, int s) {
        const uint32_t kb = sbase + QTILE + s * FSTG;
        const uint32_t vb = kb + KTILE;
        #pragma unroll
        for (int i = 0; i < 8; ++i) {           // K: 64 rows x 128 halfs
            int c = tid + i * 128;
            int row = c >> 4, col = c & 15;
            CP_ASYNC(kb + row * KROW + col * 16, Kg + (size_t)(j * 64 + row) * 1024 + col * 8);
        }
        #pragma unroll
        for (int i = 0; i < 8; ++i) {           // V: 128 rows x 64 halfs
            int c = tid + i * 128;
            int row = c >> 3, col = c & 7;
            CP_ASYNC(vb + row * VROW + col * 16, Vg + (size_t)row * NSP + j * 64 + col * 8);
        }
        CP_COMMIT();
    };
    load_kv(0, 0);
    load_kv(1, 1);
    CP_WAIT1();                // Q + chunk0 arrived
    __syncthreads();

    // Q fragments: warp owns q rows [wid*32, wid*32+32) -> 2 m-blocks
    uint32_t qf[2][8][4];
    #pragma unroll
    for (int mb = 0; mb < 2; ++mb) {
        const uint32_t base = sbase + (wid * 32 + mb * 16 + (lane & 15)) * KROW
                            + ((lane >> 4) << 4);
        #pragma unroll
        for (int k16 = 0; k16 < 8; ++k16) ldsm4(qf[mb][k16], base + k16 * 32);
    }

    uint32_t oacc[2][16][2] = {};    // f16 accumulators: [mb][n8(ch)][reg]
    float lacc[2][4] = {};           // row sums via ones-MMA (fp32)

    const uint32_t ro_k = (lane & 15) * KROW + ((lane >> 4) << 4);
    const uint32_t ro_v = (lane & 15) * VROW + ((lane >> 4) << 4);

    for (int j = 0; j < 16; ++j) {
        const int s = j & 1;
        const uint32_t kb = sbase + QTILE + s * FSTG;
        const uint32_t vb = kb + KTILE;

        // ---- per 16-kv block: S mma -> exp2 -> immediately O mma ----
        #pragma unroll
        for (int kb4 = 0; kb4 < 4; ++kb4) {
            float s00[4] = {}, s01[4] = {}, s10[4] = {}, s11[4] = {};
            const uint32_t base = kb + kb4 * 16 * KROW + ro_k;
            #pragma unroll
            for (int k16 = 0; k16 < 8; ++k16) {
                uint32_t bf[4];
                ldsm4(bf, base + k16 * 32);
                mma16816(s00, qf[0][k16], bf[0], bf[2]);
                mma16816(s01, qf[0][k16], bf[1], bf[3]);
                mma16816(s10, qf[1][k16], bf[0], bf[2]);
                mma16816(s11, qf[1][k16], bf[1], bf[3]);
            }
            uint32_t pa0[4], pa1[4];
            pa0[0] = ex2h2(pack2(s00[0], s00[1]));
            pa0[1] = ex2h2(pack2(s00[2], s00[3]));
            pa0[2] = ex2h2(pack2(s01[0], s01[1]));
            pa0[3] = ex2h2(pack2(s01[2], s01[3]));
            pa1[0] = ex2h2(pack2(s10[0], s10[1]));
            pa1[1] = ex2h2(pack2(s10[2], s10[3]));
            pa1[2] = ex2h2(pack2(s11[0], s11[1]));
            pa1[3] = ex2h2(pack2(s11[2], s11[3]));
            mma16816(lacc[0], pa0, ONESH2, ONESH2);
            mma16816(lacc[1], pa1, ONESH2, ONESH2);

            // O += P V^T for this 16-kv slice (f16 accumulate)
            #pragma unroll
            for (int cb = 0; cb < 8; ++cb) {
                uint32_t vf[4];
                ldsm4(vf, vb + cb * 16 * VROW + ro_v + kb4 * 32);
                mma16816h(oacc[0][2 * cb],     pa0, vf[0], vf[2]);
                mma16816h(oacc[0][2 * cb + 1], pa0, vf[1], vf[3]);
                mma16816h(oacc[1][2 * cb],     pa1, vf[0], vf[2]);
                mma16816h(oacc[1][2 * cb + 1], pa1, vf[1], vf[3]);
            }
        }

        if (j + 1 < 16) {
            __syncthreads();                   // stage s fully consumed
            if (j + 2 < 16) { load_kv(j + 2, s); CP_WAIT1(); }
            else            { CP_WAIT0(); }
            __syncthreads();                   // next stage visible to all
        }
    }

    // ---- epilogue: O / l -> oT[b][n][c] (fp32 scaling) ----
    const int fr = lane >> 2, fc = (lane & 3) * 2;
    ht* Ob = O + (size_t)b * (NSP * NCH) + (size_t)(q0 + wid * 32) * NCH + h * 128;
    #pragma unroll
    for (int mb = 0; mb < 2; ++mb) {
        const float i0 = 1.f / lacc[mb][0], i1 = 1.f / lacc[mb][2];
        ht* Or0 = Ob + (size_t)(mb * 16 + fr) * NCH;
        ht* Or1 = Ob + (size_t)(mb * 16 + fr + 8) * NCH;
        #pragma unroll
        for (int jn = 0; jn < 16; ++jn) {
            float2 f0 = __half22float2(*(__half2*)&oacc[mb][jn][0]);
            float2 f1 = __half22float2(*(__half2*)&oacc[mb][jn][1]);
            *(__half2*)(Or0 + jn * 8 + fc) = __floats2half2_rn(f0.x * i0, f0.y * i0);
            *(__half2*)(Or1 + jn * 8 + fc) = __floats2half2_rn(f1.x * i1, f1.y * i1);
        }
    }
}

// ------------------------------ launch ---------------------------------------
extern "C" void kernel_launch(void* const* d_in, const int* in_sizes, int n_in,
                              void* d_out, int out_size) {
    const float* x      = (const float*)d_in[0];
    const float* gamma  = (const float*)d_in[1];
    const float* beta   = (const float*)d_in[2];
    const float* w_qkv  = (const float*)d_in[3];
    const float* b_qkv  = (const float*)d_in[4];
    const float* w_proj = (const float*)d_in[5];
    const float* b_proj = (const float*)d_in[6];
    float* out = (float*)d_out;

    ht *xn, *wq, *wp, *qk, *v, *oT;
    cudaGetSymbolAddress((void**)&xn, g_xn);
    cudaGetSymbolAddress((void**)&wq, g_wq);
    cudaGetSymbolAddress((void**)&wp, g_wp);
    cudaGetSymbolAddress((void**)&qk, g_qk);
    cudaGetSymbolAddress((void**)&v,  g_v);
    cudaGetSymbolAddress((void**)&oT, g_oT);

    cudaFuncSetAttribute(gemm_mma<0>, cudaFuncAttributeMaxDynamicSharedMemorySize, SMEMSZ);
    cudaFuncSetAttribute(gemm_mma<3>, cudaFuncAttributeMaxDynamicSharedMemorySize, SMEMSZ);
    cudaFuncSetAttribute(flash_kernel, cudaFuncAttributeMaxDynamicSharedMemorySize, FSMEM);

    convw_kernel<<<4096, 256>>>(w_qkv, w_proj, wq, wp);
    groupnorm_kernel<<<NB * 32, 256>>>(x, gamma, beta, xn);

    // QKV: q/k -> qkT (transposed, q pre-scaled), v -> [b][c][m]
    gemm_mma<0><<<dim3(4, 12, NB), 256, SMEMSZ>>>(
        wq, xn, nullptr, qk, v, b_qkv, nullptr);
    // fused S + softmax + O -> oT
    flash_kernel<<<dim3(8, 64), 128, FSMEM>>>(qk, v, oT);
    // out = x + w_proj O + b_proj
    gemm_mma<3><<<dim3(4, 4, NB), 256, SMEMSZ>>>(
        wp, oT, out, nullptr, nullptr, b_proj, x);
}

// round 13
// speedup vs baseline: 1.1122x; 1.1122x over previous
#include <cuda_runtime.h>
#include <cuda_fp16.h>
#include <cstdint>
#include <math.h>

typedef __half ht;

#define NCH  512
#define NSP  1024
#define NB   16
#define CHN  (NCH*NSP)
#define QS   0.08838834764831845f
#define QSE  (0.08838834764831845f * 1.4426950408889634f)   // fold log2(e) for exp2

// --------------------------- scratch (device globals) ------------------------
__device__ ht g_xn [(size_t)NB*NSP*NCH];      // [b][n][c]
__device__ ht g_wq [1536*512];
__device__ ht g_wp [512*512];
__device__ ht g_qk [(size_t)NB*NSP*1024];     // [b][n][q(512)|k(512)]
__device__ ht g_v  [(size_t)NB*NCH*NSP];      // [b][c][m]
__device__ ht g_oT [(size_t)NB*NSP*NCH];      // [b][n][c]

// ------------------------------ PTX helpers ----------------------------------
__device__ __forceinline__ uint32_t smem_u32(const void* p) {
    uint32_t a;
    asm("{ .reg .u64 t; cvta.to.shared.u64 t, %1; cvt.u32.u64 %0, t; }" : "=r"(a) : "l"(p));
    return a;
}
__device__ __forceinline__ void ldsm4(uint32_t* r, uint32_t addr) {
    asm volatile("ldmatrix.sync.aligned.m8n8.x4.shared.b16 {%0,%1,%2,%3}, [%4];"
        : "=r"(r[0]), "=r"(r[1]), "=r"(r[2]), "=r"(r[3]) : "r"(addr));
}
__device__ __forceinline__ void mma16816(float* d, const uint32_t* a, uint32_t b0, uint32_t b1) {
    asm volatile("mma.sync.aligned.m16n8k16.row.col.f32.f16.f16.f32 "
        "{%0,%1,%2,%3}, {%4,%5,%6,%7}, {%8,%9}, {%0,%1,%2,%3};"
        : "+f"(d[0]), "+f"(d[1]), "+f"(d[2]), "+f"(d[3])
        : "r"(a[0]), "r"(a[1]), "r"(a[2]), "r"(a[3]), "r"(b0), "r"(b1));
}
__device__ __forceinline__ void mma16816h(uint32_t* d, const uint32_t* a, uint32_t b0, uint32_t b1) {
    asm volatile("mma.sync.aligned.m16n8k16.row.col.f16.f16.f16.f16 "
        "{%0,%1}, {%2,%3,%4,%5}, {%6,%7}, {%0,%1};"
        : "+r"(d[0]), "+r"(d[1])
        : "r"(a[0]), "r"(a[1]), "r"(a[2]), "r"(a[3]), "r"(b0), "r"(b1));
}
__device__ __forceinline__ uint32_t pack2(float a, float b) {
    __half2 p = __floats2half2_rn(a, b);
    return *(uint32_t*)&p;
}
__device__ __forceinline__ uint32_t ex2h2(uint32_t x) {
    uint32_t y;
    asm("ex2.approx.f16x2 %0, %1;" : "=r"(y) : "r"(x));
    return y;
}
#define CP_ASYNC(dst, src) asm volatile("cp.async.cg.shared.global [%0], [%1], 16;" :: "r"(dst), "l"(src))
#define CP_COMMIT()  asm volatile("cp.async.commit_group;" ::: "memory")
#define CP_WAIT3()   asm volatile("cp.async.wait_group 3;" ::: "memory")
#define CP_WAIT1()   asm volatile("cp.async.wait_group 1;" ::: "memory")
#define CP_WAIT0()   asm volatile("cp.async.wait_group 0;" ::: "memory")

// --------------------------- weight convert ----------------------------------
__global__ __launch_bounds__(256)
void convw_kernel(const float* __restrict__ wq, const float* __restrict__ wp,
                  ht* __restrict__ wqo, ht* __restrict__ wpo) {
    int i = blockIdx.x * 256 + threadIdx.x;
    if (i < 1536*512) {
        float v = wq[i];
        if (i < 512*512) v *= QSE;                // fold (1/sqrt(hd))*log2(e) into w_q
        wqo[i] = __float2half_rn(v);
    } else {
        int j = i - 1536*512;
        if (j < 512*512) wpo[j] = __float2half_rn(wp[j]);
    }
}

// ------------------------------ GroupNorm ------------------------------------
__global__ __launch_bounds__(256)
void groupnorm_kernel(const float* __restrict__ x, const float* __restrict__ gamma,
                      const float* __restrict__ beta, ht* __restrict__ xn) {
    const int b = blockIdx.x >> 5, g = blockIdx.x & 31;
    const float* xp = x + (size_t)b * CHN + (size_t)g * (16 * NSP);

    float s = 0.f, s2 = 0.f;
    for (int i = threadIdx.x; i < 16 * NSP; i += 256) {
        float v = xp[i]; s += v; s2 += v * v;
    }
    __shared__ float rs[8], rs2[8];
    for (int o = 16; o; o >>= 1) {
        s  += __shfl_xor_sync(0xffffffffu, s,  o);
        s2 += __shfl_xor_sync(0xffffffffu, s2, o);
    }
    int wid = threadIdx.x >> 5;
    if ((threadIdx.x & 31) == 0) { rs[wid] = s; rs2[wid] = s2; }
    __syncthreads();
    s = 0.f; s2 = 0.f;
    #pragma unroll
    for (int i = 0; i < 8; i++) { s += rs[i]; s2 += rs2[i]; }
    const float inv = 1.0f / (16 * NSP);
    float mu = s * inv;
    float rstd = rsqrtf(s2 * inv - mu * mu + 1e-5f);

    const int gc = g * 16;
    for (int n = threadIdx.x; n < NSP; n += 256) {
        union { ht h[16]; uint4 u[2]; } H;
        #pragma unroll
        for (int c = 0; c < 16; ++c) {
            float v = (xp[c * NSP + n] - mu) * rstd * gamma[gc + c] + beta[gc + c];
            H.h[c] = __float2half_rn(v);
        }
        uint4* dh = (uint4*)(g_xn + (size_t)b * (NSP * NCH) + (size_t)n * NCH + gc);
        dh[0] = H.u[0]; dh[1] = H.u[1];
    }
}

// --------------------------- mma.sync GEMM v3 --------------------------------
// 128 threads, 4 warps as 2(M) x 2(N), warp tile 64x64, CTA tile 128x128.
// 4 MMAs per ldsm.x4; 80KB smem -> 2 CTAs/SM; regs ~200 -> 51K/SM (fits).
// MODE 0: QKV  (z=b) M=1536 N=1024 K=512 : q/k -> qkT transposed, v -> [b][c][m]
// MODE 3: proj (z=b) M=512  N=1024 K=512 : fp32 out (+bias+x)
#define SROW   80
#define ATILE  10240       // 128 * 80
#define STAGEB 20480       // A + B
#define NSTAGE 4
#define SMEMSZ (NSTAGE*STAGEB)   // 81920

template<int MODE>
__global__ __launch_bounds__(128, 2)
void gemm_mma(const ht* __restrict__ Ap, const ht* __restrict__ Bp,
              float* __restrict__ C,
              ht* __restrict__ Oh, ht* __restrict__ Vh,
              const float* __restrict__ bias, const float* __restrict__ resid) {
    extern __shared__ char smem[];
    const uint32_t sbase = smem_u32(smem);
    const int tid = threadIdx.x, lane = tid & 31, wid = tid >> 5;
    const int wm = wid >> 1, wn = wid & 1;       // 2 warps M, 2 warps N
    const int m_w = wm * 64, n_w = wn * 64;
    const int z = blockIdx.z, m0 = blockIdx.y * 128, n0 = blockIdx.x * 128;

    const int lda = 512, ldb = 512, Ktot = 512;
    const size_t aoff = (size_t)m0 * 512;
    const size_t boff = (size_t)z * (NSP * NCH) + (size_t)n0 * 512;

    float acc[4][8][4] = {};
    const int NIT = Ktot / 32;

    // 1024 16B-chunks/stage (A 512 + B 512), 8 per thread
    auto load_stage = [&](int it, int s) {
        const int k0 = it * 32;
        const uint32_t sb = sbase + s * STAGEB;
        #pragma unroll
        for (int i = 0; i < 8; ++i) {
            int c = tid + i * 128;
            int row = (c >> 2) & 127, col = c & 3;
            if (i < 4) {
                CP_ASYNC(sb + row * SROW + col * 16,
                         Ap + aoff + (size_t)row * lda + k0 + col * 8);
            } else {
                CP_ASYNC(sb + ATILE + row * SROW + col * 16,
                         Bp + boff + (size_t)row * ldb + k0 + col * 8);
            }
        }
        CP_COMMIT();
    };

    #pragma unroll
    for (int p = 0; p < NSTAGE - 1; ++p)
        if (p < NIT) load_stage(p, p);

    for (int it = 0; it < NIT; ++it) {
        const int s = it & (NSTAGE - 1);
        if (it + NSTAGE - 1 < NIT) {
            load_stage(it + NSTAGE - 1, (it + NSTAGE - 1) & (NSTAGE - 1));
            CP_WAIT3();
        } else {
            CP_WAIT0();
        }
        __syncthreads();

        const uint32_t ab = sbase + s * STAGEB;
        const uint32_t rofs = (lane & 15) * SROW + ((lane >> 4) << 4);
        #pragma unroll
        for (int k16 = 0; k16 < 2; ++k16) {
            const uint32_t ko = k16 * 32 + rofs;
            uint32_t bfr[4][4];
            #pragma unroll
            for (int j = 0; j < 4; ++j)
                ldsm4(bfr[j], ab + ATILE + (n_w + j * 16) * SROW + ko);
            uint32_t af[4][4];
            #pragma unroll
            for (int i = 0; i < 4; ++i)
                ldsm4(af[i], ab + (m_w + i * 16) * SROW + ko);
            #pragma unroll
            for (int i = 0; i < 4; ++i)
                #pragma unroll
                for (int jn = 0; jn < 8; ++jn)
                    mma16816(acc[i][jn], af[i],
                             bfr[jn >> 1][jn & 1], bfr[jn >> 1][(jn & 1) + 2]);
        }
        __syncthreads();
    }

    const int fr = lane >> 2;
    const int fc = (lane & 3) * 2;

    if (MODE == 3) {
        #pragma unroll
        for (int i = 0; i < 4; ++i)
            #pragma unroll
            for (int jn = 0; jn < 8; ++jn)
                #pragma unroll
                for (int rh = 0; rh < 2; ++rh) {
                    int row = m0 + m_w + i * 16 + fr + rh * 8;
                    int col = n0 + n_w + jn * 8 + fc;
                    float bv = bias[row];
                    const float2 xv = *(const float2*)(resid + (size_t)z * CHN + (size_t)row * NSP + col);
                    *(float2*)(C + (size_t)z * CHN + (size_t)row * NSP + col) =
                        make_float2(acc[i][jn][rh * 2] + bv + xv.x,
                                    acc[i][jn][rh * 2 + 1] + bv + xv.y);
                }
    } else if (MODE == 0 && m0 >= 1024) {
        // V region: [b][c][m]
        #pragma unroll
        for (int i = 0; i < 4; ++i)
            #pragma unroll
            for (int jn = 0; jn < 8; ++jn)
                #pragma unroll
                for (int rh = 0; rh < 2; ++rh) {
                    int mi = m_w + i * 16 + fr + rh * 8;
                    float bv = bias[m0 + mi];
                    int cc2 = m0 - 1024 + mi;
                    size_t off = (size_t)z * (NCH * NSP) + (size_t)cc2 * NSP + n0 + n_w + jn * 8 + fc;
                    *(__half2*)(Vh + off) = __halves2half2(
                        __float2half_rn(acc[i][jn][rh * 2] + bv),
                        __float2half_rn(acc[i][jn][rh * 2 + 1] + bv));
                }
    } else {
        // q/k region -> transposed qkT; two n-halves of 64
        uint32_t* TB = (uint32_t*)smem;       // [64 n][132 m]
        #pragma unroll
        for (int hh = 0; hh < 2; ++hh) {
            __syncthreads();
            if (wn == hh) {
                #pragma unroll
                for (int i = 0; i < 4; ++i)
                    #pragma unroll
                    for (int jn = 0; jn < 8; ++jn)
                        #pragma unroll
                        for (int rh = 0; rh < 2; ++rh) {
                            int mi = m_w + i * 16 + fr + rh * 8;
                            float bv = bias[m0 + mi];
                            if (m0 < 512) bv *= QSE;
                            float v0 = acc[i][jn][rh * 2] + bv;
                            float v1 = acc[i][jn][rh * 2 + 1] + bv;
                            int ncl = jn * 8 + fc;
                            TB[ncl * 132 + mi]       = (uint32_t)__half_as_ushort(__float2half_rn(v0));
                            TB[(ncl + 1) * 132 + mi] = (uint32_t)__half_as_ushort(__float2half_rn(v1));
                        }
            }
            __syncthreads();
            int rr = tid >> 1, seg = (tid & 1) * 64;
            size_t nco = (size_t)z * (NSP * 1024) + (size_t)(n0 + hh * 64 + rr) * 1024 + m0 + seg;
            #pragma unroll
            for (int q4 = 0; q4 < 8; ++q4) {
                union { ht h[8]; uint4 u; } H;
                #pragma unroll
                for (int e = 0; e < 8; ++e)
                    H.h[e] = __ushort_as_half((unsigned short)(TB[rr * 132 + seg + q4 * 8 + e] & 0xffffu));
                *(uint4*)(Oh + nco + q4 * 8) = H.u;
            }
        }
    }
}

// ------------------------- flash attention v4 (R11 best) ---------------------
// 128 threads (4 warps), q-tile 128 (32 q rows/warp), kv-chunk 64, 2 CTAs/SM.
#define KROW  272                  // 128 halfs + 16B pad
#define VROW  144                  // 64 halfs + 16B pad
#define QTILE (128*KROW)           // 34816
#define KTILE (64*KROW)            // 17408
#define VTILE (128*VROW)           // 18432
#define FSTG  (KTILE+VTILE)        // 35840
#define FSMEM (QTILE + 2*FSTG)     // 106496
#define ONESH2 0x3C003C00u

__global__ __launch_bounds__(128, 2)
void flash_kernel(const ht* __restrict__ QK, const ht* __restrict__ Vg_,
                  ht* __restrict__ O) {
    extern __shared__ char smem[];
    const uint32_t sbase = smem_u32(smem);
    const int tid = threadIdx.x, lane = tid & 31, wid = tid >> 5;
    const int z = blockIdx.y, b = z >> 2, h = z & 3;
    const int q0 = blockIdx.x * 128;

    const ht* Qg = QK  + (size_t)b * (NSP * 1024) + (size_t)q0 * 1024 + h * 128;
    const ht* Kg = QK  + (size_t)b * (NSP * 1024) + 512 + h * 128;
    const ht* Vg = Vg_ + (size_t)b * CHN + (size_t)(h * 128) * NSP;

    // Q tile: 128 rows x 128 halfs = 2048 16B chunks, 16/thread
    #pragma unroll
    for (int i = 0; i < 16; ++i) {
        int c = tid + i * 128;
        int row = c >> 4, col = c & 15;
        CP_ASYNC(sbase + row * KROW + col * 16, Qg + (size_t)row * 1024 + col * 8);
    }
    CP_COMMIT();

    auto load_kv = [&](int j, int s) {
        const uint32_t kb = sbase + QTILE + s * FSTG;
        const uint32_t vb = kb + KTILE;
        #pragma unroll
        for (int i = 0; i < 8; ++i) {           // K: 64 rows x 128 halfs
            int c = tid + i * 128;
            int row = c >> 4, col = c & 15;
            CP_ASYNC(kb + row * KROW + col * 16, Kg + (size_t)(j * 64 + row) * 1024 + col * 8);
        }
        #pragma unroll
        for (int i = 0; i < 8; ++i) {           // V: 128 rows x 64 halfs
            int c = tid + i * 128;
            int row = c >> 3, col = c & 7;
            CP_ASYNC(vb + row * VROW + col * 16, Vg + (size_t)row * NSP + j * 64 + col * 8);
        }
        CP_COMMIT();
    };
    load_kv(0, 0);
    load_kv(1, 1);
    CP_WAIT1();                // Q + chunk0 arrived
    __syncthreads();

    // Q fragments: warp owns q rows [wid*32, wid*32+32) -> 2 m-blocks
    uint32_t qf[2][8][4];
    #pragma unroll
    for (int mb = 0; mb < 2; ++mb) {
        const uint32_t base = sbase + (wid * 32 + mb * 16 + (lane & 15)) * KROW
                            + ((lane >> 4) << 4);
        #pragma unroll
        for (int k16 = 0; k16 < 8; ++k16) ldsm4(qf[mb][k16], base + k16 * 32);
    }

    uint32_t oacc[2][16][2] = {};    // f16 accumulators: [mb][n8(ch)][reg]
    float lacc[2][4] = {};           // row sums via ones-MMA (fp32)

    const uint32_t ro_k = (lane & 15) * KROW + ((lane >> 4) << 4);
    const uint32_t ro_v = (lane & 15) * VROW + ((lane >> 4) << 4);

    for (int j = 0; j < 16; ++j) {
        const int s = j & 1;
        const uint32_t kb = sbase + QTILE + s * FSTG;
        const uint32_t vb = kb + KTILE;

        // ---- S = Q K^T per 16-kv block, pack+exp2 -> P fragments ----
        uint32_t pa[2][4][4];        // [mb][kb4][reg]
        #pragma unroll
        for (int kb4 = 0; kb4 < 4; ++kb4) {
            float s00[4] = {}, s01[4] = {}, s10[4] = {}, s11[4] = {};
            const uint32_t base = kb + kb4 * 16 * KROW + ro_k;
            #pragma unroll
            for (int k16 = 0; k16 < 8; ++k16) {
                uint32_t bf[4];
                ldsm4(bf, base + k16 * 32);
                mma16816(s00, qf[0][k16], bf[0], bf[2]);
                mma16816(s01, qf[0][k16], bf[1], bf[3]);
                mma16816(s10, qf[1][k16], bf[0], bf[2]);
                mma16816(s11, qf[1][k16], bf[1], bf[3]);
            }
            pa[0][kb4][0] = ex2h2(pack2(s00[0], s00[1]));
            pa[0][kb4][1] = ex2h2(pack2(s00[2], s00[3]));
            pa[0][kb4][2] = ex2h2(pack2(s01[0], s01[1]));
            pa[0][kb4][3] = ex2h2(pack2(s01[2], s01[3]));
            pa[1][kb4][0] = ex2h2(pack2(s10[0], s10[1]));
            pa[1][kb4][1] = ex2h2(pack2(s10[2], s10[3]));
            pa[1][kb4][2] = ex2h2(pack2(s11[0], s11[1]));
            pa[1][kb4][3] = ex2h2(pack2(s11[2], s11[3]));
            mma16816(lacc[0], pa[0][kb4], ONESH2, ONESH2);
            mma16816(lacc[1], pa[1][kb4], ONESH2, ONESH2);
        }

        // ---- O += P V^T (f16 accumulate) ----
        #pragma unroll
        for (int kb4 = 0; kb4 < 4; ++kb4) {
            #pragma unroll
            for (int cb = 0; cb < 8; ++cb) {
                uint32_t vf[4];
                ldsm4(vf, vb + cb * 16 * VROW + ro_v + kb4 * 32);
                mma16816h(oacc[0][2 * cb],     pa[0][kb4], vf[0], vf[2]);
                mma16816h(oacc[0][2 * cb + 1], pa[0][kb4], vf[1], vf[3]);
                mma16816h(oacc[1][2 * cb],     pa[1][kb4], vf[0], vf[2]);
                mma16816h(oacc[1][2 * cb + 1], pa[1][kb4], vf[1], vf[3]);
            }
        }

        if (j + 1 < 16) {
            __syncthreads();                   // stage s fully consumed
            if (j + 2 < 16) { load_kv(j + 2, s); CP_WAIT1(); }
            else            { CP_WAIT0(); }
            __syncthreads();                   // next stage visible to all
        }
    }

    // ---- epilogue: O / l -> oT[b][n][c] (fp32 scaling) ----
    const int fr = lane >> 2, fc = (lane & 3) * 2;
    ht* Ob = O + (size_t)b * (NSP * NCH) + (size_t)(q0 + wid * 32) * NCH + h * 128;
    #pragma unroll
    for (int mb = 0; mb < 2; ++mb) {
        const float i0 = 1.f / lacc[mb][0], i1 = 1.f / lacc[mb][2];
        ht* Or0 = Ob + (size_t)(mb * 16 + fr) * NCH;
        ht* Or1 = Ob + (size_t)(mb * 16 + fr + 8) * NCH;
        #pragma unroll
        for (int jn = 0; jn < 16; ++jn) {
            float2 f0 = __half22float2(*(__half2*)&oacc[mb][jn][0]);
            float2 f1 = __half22float2(*(__half2*)&oacc[mb][jn][1]);
            *(__half2*)(Or0 + jn * 8 + fc) = __floats2half2_rn(f0.x * i0, f0.y * i0);
            *(__half2*)(Or1 + jn * 8 + fc) = __floats2half2_rn(f1.x * i1, f1.y * i1);
        }
    }
}

// ------------------------------ launch ---------------------------------------
extern "C" void kernel_launch(void* const* d_in, const int* in_sizes, int n_in,
                              void* d_out, int out_size) {
    const float* x      = (const float*)d_in[0];
    const float* gamma  = (const float*)d_in[1];
    const float* beta   = (const float*)d_in[2];
    const float* w_qkv  = (const float*)d_in[3];
    const float* b_qkv  = (const float*)d_in[4];
    const float* w_proj = (const float*)d_in[5];
    const float* b_proj = (const float*)d_in[6];
    float* out = (float*)d_out;

    ht *xn, *wq, *wp, *qk, *v, *oT;
    cudaGetSymbolAddress((void**)&xn, g_xn);
    cudaGetSymbolAddress((void**)&wq, g_wq);
    cudaGetSymbolAddress((void**)&wp, g_wp);
    cudaGetSymbolAddress((void**)&qk, g_qk);
    cudaGetSymbolAddress((void**)&v,  g_v);
    cudaGetSymbolAddress((void**)&oT, g_oT);

    cudaFuncSetAttribute(gemm_mma<0>, cudaFuncAttributeMaxDynamicSharedMemorySize, SMEMSZ);
    cudaFuncSetAttribute(gemm_mma<3>, cudaFuncAttributeMaxDynamicSharedMemorySize, SMEMSZ);
    cudaFuncSetAttribute(flash_kernel, cudaFuncAttributeMaxDynamicSharedMemorySize, FSMEM);

    convw_kernel<<<4096, 256>>>(w_qkv, w_proj, wq, wp);
    groupnorm_kernel<<<NB * 32, 256>>>(x, gamma, beta, xn);

    // QKV: q/k -> qkT (transposed, q pre-scaled), v -> [b][c][m]
    gemm_mma<0><<<dim3(8, 12, NB), 128, SMEMSZ>>>(
        wq, xn, nullptr, qk, v, b_qkv, nullptr);
    // fused S + softmax + O -> oT
    flash_kernel<<<dim3(8, 64), 128, FSMEM>>>(qk, v, oT);
    // out = x + w_proj O + b_proj
    gemm_mma<3><<<dim3(8, 4, NB), 128, SMEMSZ>>>(
        wp, oT, out, nullptr, nullptr, b_proj, x);
}

// round 14
// speedup vs baseline: 1.1769x; 1.0582x over previous
#include <cuda_runtime.h>
#include <cuda_fp16.h>
#include <cstdint>
#include <math.h>

typedef __half ht;

#define NCH  512
#define NSP  1024
#define NB   16
#define CHN  (NCH*NSP)
#define QS   0.08838834764831845f
#define QSE  (0.08838834764831845f * 1.4426950408889634f)   // fold log2(e) for exp2

// --------------------------- scratch (device globals) ------------------------
__device__ ht g_xn [(size_t)NB*NSP*NCH];      // [b][n][c]
__device__ ht g_wq [1536*512];
__device__ ht g_wp [512*512];
__device__ ht g_qk [(size_t)NB*NSP*1024];     // [b][n][q(512)|k(512)]
__device__ ht g_v  [(size_t)NB*NCH*NSP];      // [b][c][m]
__device__ ht g_oT [(size_t)NB*NSP*NCH];      // [b][n][c]

// ------------------------------ PTX helpers ----------------------------------
__device__ __forceinline__ uint32_t smem_u32(const void* p) {
    uint32_t a;
    asm("{ .reg .u64 t; cvta.to.shared.u64 t, %1; cvt.u32.u64 %0, t; }" : "=r"(a) : "l"(p));
    return a;
}
__device__ __forceinline__ void ldsm4(uint32_t* r, uint32_t addr) {
    asm volatile("ldmatrix.sync.aligned.m8n8.x4.shared.b16 {%0,%1,%2,%3}, [%4];"
        : "=r"(r[0]), "=r"(r[1]), "=r"(r[2]), "=r"(r[3]) : "r"(addr));
}
__device__ __forceinline__ void mma16816(float* d, const uint32_t* a, uint32_t b0, uint32_t b1) {
    asm volatile("mma.sync.aligned.m16n8k16.row.col.f32.f16.f16.f32 "
        "{%0,%1,%2,%3}, {%4,%5,%6,%7}, {%8,%9}, {%0,%1,%2,%3};"
        : "+f"(d[0]), "+f"(d[1]), "+f"(d[2]), "+f"(d[3])
        : "r"(a[0]), "r"(a[1]), "r"(a[2]), "r"(a[3]), "r"(b0), "r"(b1));
}
__device__ __forceinline__ void mma16816h(uint32_t* d, const uint32_t* a, uint32_t b0, uint32_t b1) {
    asm volatile("mma.sync.aligned.m16n8k16.row.col.f16.f16.f16.f16 "
        "{%0,%1}, {%2,%3,%4,%5}, {%6,%7}, {%0,%1};"
        : "+r"(d[0]), "+r"(d[1])
        : "r"(a[0]), "r"(a[1]), "r"(a[2]), "r"(a[3]), "r"(b0), "r"(b1));
}
__device__ __forceinline__ uint32_t pack2(float a, float b) {
    __half2 p = __floats2half2_rn(a, b);
    return *(uint32_t*)&p;
}
__device__ __forceinline__ uint32_t ex2h2(uint32_t x) {
    uint32_t y;
    asm("ex2.approx.f16x2 %0, %1;" : "=r"(y) : "r"(x));
    return y;
}
#define CP_ASYNC(dst, src) asm volatile("cp.async.cg.shared.global [%0], [%1], 16;" :: "r"(dst), "l"(src))
#define CP_COMMIT()  asm volatile("cp.async.commit_group;" ::: "memory")
#define CP_WAIT2()   asm volatile("cp.async.wait_group 2;" ::: "memory")
#define CP_WAIT1()   asm volatile("cp.async.wait_group 1;" ::: "memory")
#define CP_WAIT0()   asm volatile("cp.async.wait_group 0;" ::: "memory")

// ----------------- prep: groupnorm (blocks 0..511) + weight convert ----------
__global__ __launch_bounds__(256)
void prep_kernel(const float* __restrict__ x, const float* __restrict__ gamma,
                 const float* __restrict__ beta, ht* __restrict__ xn,
                 const float* __restrict__ wq, const float* __restrict__ wp,
                 ht* __restrict__ wqo, ht* __restrict__ wpo) {
    if (blockIdx.x >= 512) {
        int i = (blockIdx.x - 512) * 256 + threadIdx.x;
        if (i < 1536*512) {
            float v = wq[i];
            if (i < 512*512) v *= QSE;            // fold (1/sqrt(hd))*log2(e) into w_q
            wqo[i] = __float2half_rn(v);
        } else {
            int j = i - 1536*512;
            if (j < 512*512) wpo[j] = __float2half_rn(wp[j]);
        }
        return;
    }
    const int b = blockIdx.x >> 5, g = blockIdx.x & 31;
    const float* xp = x + (size_t)b * CHN + (size_t)g * (16 * NSP);

    float s = 0.f, s2 = 0.f;
    for (int i = threadIdx.x; i < 16 * NSP; i += 256) {
        float v = xp[i]; s += v; s2 += v * v;
    }
    __shared__ float rs[8], rs2[8];
    for (int o = 16; o; o >>= 1) {
        s  += __shfl_xor_sync(0xffffffffu, s,  o);
        s2 += __shfl_xor_sync(0xffffffffu, s2, o);
    }
    int wid = threadIdx.x >> 5;
    if ((threadIdx.x & 31) == 0) { rs[wid] = s; rs2[wid] = s2; }
    __syncthreads();
    s = 0.f; s2 = 0.f;
    #pragma unroll
    for (int i = 0; i < 8; i++) { s += rs[i]; s2 += rs2[i]; }
    const float inv = 1.0f / (16 * NSP);
    float mu = s * inv;
    float rstd = rsqrtf(s2 * inv - mu * mu + 1e-5f);

    const int gc = g * 16;
    for (int n = threadIdx.x; n < NSP; n += 256) {
        union { ht h[16]; uint4 u[2]; } H;
        #pragma unroll
        for (int c = 0; c < 16; ++c) {
            float v = (xp[c * NSP + n] - mu) * rstd * gamma[gc + c] + beta[gc + c];
            H.h[c] = __float2half_rn(v);
        }
        uint4* dh = (uint4*)(xn + (size_t)b * (NSP * NCH) + (size_t)n * NCH + gc);
        dh[0] = H.u[0]; dh[1] = H.u[1];
    }
}

// --------------------------- mma.sync GEMM v3.1 ------------------------------
// 128 threads, 4 warps as 2(M) x 2(N), warp tile 64x64, CTA tile 128x128.
// 4-stage cp.async, ONE __syncthreads per k-iteration.
// MODE 0: QKV  (z=b) M=1536 N=1024 K=512 : q/k -> qkT transposed, v -> [b][c][m]
// MODE 3: proj (z=b) M=512  N=1024 K=512 : fp32 out (+bias+x)
#define SROW   80
#define ATILE  10240       // 128 * 80
#define STAGEB 20480       // A + B
#define NSTAGE 4
#define SMEMSZ (NSTAGE*STAGEB)   // 81920

template<int MODE>
__global__ __launch_bounds__(128, 2)
void gemm_mma(const ht* __restrict__ Ap, const ht* __restrict__ Bp,
              float* __restrict__ C,
              ht* __restrict__ Oh, ht* __restrict__ Vh,
              const float* __restrict__ bias, const float* __restrict__ resid) {
    extern __shared__ char smem[];
    const uint32_t sbase = smem_u32(smem);
    const int tid = threadIdx.x, lane = tid & 31, wid = tid >> 5;
    const int wm = wid >> 1, wn = wid & 1;       // 2 warps M, 2 warps N
    const int m_w = wm * 64, n_w = wn * 64;
    const int z = blockIdx.z, m0 = blockIdx.y * 128, n0 = blockIdx.x * 128;

    const int lda = 512, ldb = 512, Ktot = 512;
    const size_t aoff = (size_t)m0 * 512;
    const size_t boff = (size_t)z * (NSP * NCH) + (size_t)n0 * 512;

    float acc[4][8][4] = {};
    const int NIT = Ktot / 32;

    auto load_stage = [&](int it, int s) {
        const int k0 = it * 32;
        const uint32_t sb = sbase + s * STAGEB;
        #pragma unroll
        for (int i = 0; i < 8; ++i) {
            int c = tid + i * 128;
            int row = (c >> 2) & 127, col = c & 3;
            if (i < 4) {
                CP_ASYNC(sb + row * SROW + col * 16,
                         Ap + aoff + (size_t)row * lda + k0 + col * 8);
            } else {
                CP_ASYNC(sb + ATILE + row * SROW + col * 16,
                         Bp + boff + (size_t)row * ldb + k0 + col * 8);
            }
        }
        CP_COMMIT();
    };

    load_stage(0, 0); load_stage(1, 1); load_stage(2, 2);

    for (int it = 0; it < NIT; ++it) {
        const int s = it & (NSTAGE - 1);
        if (it + 2 < NIT)      { CP_WAIT2(); }
        else if (it + 1 < NIT) { CP_WAIT1(); }
        else                   { CP_WAIT0(); }
        __syncthreads();

        const uint32_t ab = sbase + s * STAGEB;
        const uint32_t rofs = (lane & 15) * SROW + ((lane >> 4) << 4);
        #pragma unroll
        for (int k16 = 0; k16 < 2; ++k16) {
            const uint32_t ko = k16 * 32 + rofs;
            uint32_t bfr[4][4];
            #pragma unroll
            for (int j = 0; j < 4; ++j)
                ldsm4(bfr[j], ab + ATILE + (n_w + j * 16) * SROW + ko);
            uint32_t af[4][4];
            #pragma unroll
            for (int i = 0; i < 4; ++i)
                ldsm4(af[i], ab + (m_w + i * 16) * SROW + ko);
            #pragma unroll
            for (int i = 0; i < 4; ++i)
                #pragma unroll
                for (int jn = 0; jn < 8; ++jn)
                    mma16816(acc[i][jn], af[i],
                             bfr[jn >> 1][jn & 1], bfr[jn >> 1][(jn & 1) + 2]);
        }
        if (it + 3 < NIT) load_stage(it + 3, (it + 3) & (NSTAGE - 1));
    }

    const int fr = lane >> 2;
    const int fc = (lane & 3) * 2;

    if (MODE == 3) {
        #pragma unroll
        for (int i = 0; i < 4; ++i)
            #pragma unroll
            for (int jn = 0; jn < 8; ++jn)
                #pragma unroll
                for (int rh = 0; rh < 2; ++rh) {
                    int row = m0 + m_w + i * 16 + fr + rh * 8;
                    int col = n0 + n_w + jn * 8 + fc;
                    float bv = bias[row];
                    const float2 xv = *(const float2*)(resid + (size_t)z * CHN + (size_t)row * NSP + col);
                    *(float2*)(C + (size_t)z * CHN + (size_t)row * NSP + col) =
                        make_float2(acc[i][jn][rh * 2] + bv + xv.x,
                                    acc[i][jn][rh * 2 + 1] + bv + xv.y);
                }
    } else if (MODE == 0 && m0 >= 1024) {
        // V region: [b][c][m]
        #pragma unroll
        for (int i = 0; i < 4; ++i)
            #pragma unroll
            for (int jn = 0; jn < 8; ++jn)
                #pragma unroll
                for (int rh = 0; rh < 2; ++rh) {
                    int mi = m_w + i * 16 + fr + rh * 8;
                    float bv = bias[m0 + mi];
                    int cc2 = m0 - 1024 + mi;
                    size_t off = (size_t)z * (NCH * NSP) + (size_t)cc2 * NSP + n0 + n_w + jn * 8 + fc;
                    *(__half2*)(Vh + off) = __halves2half2(
                        __float2half_rn(acc[i][jn][rh * 2] + bv),
                        __float2half_rn(acc[i][jn][rh * 2 + 1] + bv));
                }
    } else {
        // q/k region -> transposed qkT; two n-halves of 64
        uint32_t* TB = (uint32_t*)smem;       // [64 n][132 m]
        #pragma unroll
        for (int hh = 0; hh < 2; ++hh) {
            __syncthreads();
            if (wn == hh) {
                #pragma unroll
                for (int i = 0; i < 4; ++i)
                    #pragma unroll
                    for (int jn = 0; jn < 8; ++jn)
                        #pragma unroll
                        for (int rh = 0; rh < 2; ++rh) {
                            int mi = m_w + i * 16 + fr + rh * 8;
                            float bv = bias[m0 + mi];
                            if (m0 < 512) bv *= QSE;
                            float v0 = acc[i][jn][rh * 2] + bv;
                            float v1 = acc[i][jn][rh * 2 + 1] + bv;
                            int ncl = jn * 8 + fc;
                            TB[ncl * 132 + mi]       = (uint32_t)__half_as_ushort(__float2half_rn(v0));
                            TB[(ncl + 1) * 132 + mi] = (uint32_t)__half_as_ushort(__float2half_rn(v1));
                        }
            }
            __syncthreads();
            int rr = tid >> 1, seg = (tid & 1) * 64;
            size_t nco = (size_t)z * (NSP * 1024) + (size_t)(n0 + hh * 64 + rr) * 1024 + m0 + seg;
            #pragma unroll
            for (int q4 = 0; q4 < 8; ++q4) {
                union { ht h[8]; uint4 u; } H;
                #pragma unroll
                for (int e = 0; e < 8; ++e)
                    H.h[e] = __ushort_as_half((unsigned short)(TB[rr * 132 + seg + q4 * 8 + e] & 0xffffu));
                *(uint4*)(Oh + nco + q4 * 8) = H.u;
            }
        }
    }
}

// ------------------------- flash attention v5 --------------------------------
// 128 threads (4 warps), q-tile 128 (32 q rows/warp), kv-chunk 64, 2 CTAs/SM.
// 3-stage KV ring; Q overlays stage 2 (register-resident after prologue).
// ONE __syncthreads per kv-iteration.
#define KROW  272                  // 128 halfs + 16B pad
#define VROW  144                  // 64 halfs + 16B pad
#define KTILE (64*KROW)            // 17408
#define VTILE (128*VROW)           // 18432
#define FSTG  (KTILE+VTILE)        // 35840
#define FSMEM (3*FSTG)             // 107520
#define QOFF  (2*FSTG)             // Q tile overlays stage 2
#define ONESH2 0x3C003C00u

__global__ __launch_bounds__(128, 2)
void flash_kernel(const ht* __restrict__ QK, const ht* __restrict__ Vg_,
                  ht* __restrict__ O) {
    extern __shared__ char smem[];
    const uint32_t sbase = smem_u32(smem);
    const int tid = threadIdx.x, lane = tid & 31, wid = tid >> 5;
    const int z = blockIdx.y, b = z >> 2, h = z & 3;
    const int q0 = blockIdx.x * 128;

    const ht* Qg = QK  + (size_t)b * (NSP * 1024) + (size_t)q0 * 1024 + h * 128;
    const ht* Kg = QK  + (size_t)b * (NSP * 1024) + 512 + h * 128;
    const ht* Vg = Vg_ + (size_t)b * CHN + (size_t)(h * 128) * NSP;

    auto load_kv = [&](int j, int s) {
        const uint32_t kb = sbase + s * FSTG;
        const uint32_t vb = kb + KTILE;
        #pragma unroll
        for (int i = 0; i < 8; ++i) {           // K: 64 rows x 128 halfs
            int c = tid + i * 128;
            int row = c >> 4, col = c & 15;
            CP_ASYNC(kb + row * KROW + col * 16, Kg + (size_t)(j * 64 + row) * 1024 + col * 8);
        }
        #pragma unroll
        for (int i = 0; i < 8; ++i) {           // V: 128 rows x 64 halfs
            int c = tid + i * 128;
            int row = c >> 3, col = c & 7;
            CP_ASYNC(vb + row * VROW + col * 16, Vg + (size_t)row * NSP + j * 64 + col * 8);
        }
        CP_COMMIT();
    };

    // Q tile -> QOFF (group 1)
    #pragma unroll
    for (int i = 0; i < 16; ++i) {
        int c = tid + i * 128;
        int row = c >> 4, col = c & 15;
        CP_ASYNC(sbase + QOFF + row * KROW + col * 16, Qg + (size_t)row * 1024 + col * 8);
    }
    CP_COMMIT();
    load_kv(0, 0);                 // group 2
    load_kv(1, 1);                 // group 3
    CP_WAIT1();                    // Q + KV0 complete
    __syncthreads();

    // Q fragments: warp owns q rows [wid*32, wid*32+32) -> 2 m-blocks
    uint32_t qf[2][8][4];
    #pragma unroll
    for (int mb = 0; mb < 2; ++mb) {
        const uint32_t base = sbase + QOFF + (wid * 32 + mb * 16 + (lane & 15)) * KROW
                            + ((lane >> 4) << 4);
        #pragma unroll
        for (int k16 = 0; k16 < 8; ++k16) ldsm4(qf[mb][k16], base + k16 * 32);
    }

    uint32_t oacc[2][16][2] = {};    // f16 accumulators: [mb][n8(ch)][reg]
    float lacc[2][4] = {};           // row sums via ones-MMA (fp32)

    const uint32_t ro_k = (lane & 15) * KROW + ((lane >> 4) << 4);
    const uint32_t ro_v = (lane & 15) * VROW + ((lane >> 4) << 4);

    for (int j = 0; j < 16; ++j) {
        const int s = j % 3;
        if (j + 1 < 16) { CP_WAIT1(); } else { CP_WAIT0(); }
        __syncthreads();            // stage s visible; also fences Q reads (j==0)

        const uint32_t kb = sbase + s * FSTG;
        const uint32_t vb = kb + KTILE;

        // ---- S = Q K^T per 16-kv block, pack+exp2 -> P fragments ----
        uint32_t pa[2][4][4];        // [mb][kb4][reg]
        #pragma unroll
        for (int kb4 = 0; kb4 < 4; ++kb4) {
            float s00[4] = {}, s01[4] = {}, s10[4] = {}, s11[4] = {};
            const uint32_t base = kb + kb4 * 16 * KROW + ro_k;
            #pragma unroll
            for (int k16 = 0; k16 < 8; ++k16) {
                uint32_t bf[4];
                ldsm4(bf, base + k16 * 32);
                mma16816(s00, qf[0][k16], bf[0], bf[2]);
                mma16816(s01, qf[0][k16], bf[1], bf[3]);
                mma16816(s10, qf[1][k16], bf[0], bf[2]);
                mma16816(s11, qf[1][k16], bf[1], bf[3]);
            }
            pa[0][kb4][0] = ex2h2(pack2(s00[0], s00[1]));
            pa[0][kb4][1] = ex2h2(pack2(s00[2], s00[3]));
            pa[0][kb4][2] = ex2h2(pack2(s01[0], s01[1]));
            pa[0][kb4][3] = ex2h2(pack2(s01[2], s01[3]));
            pa[1][kb4][0] = ex2h2(pack2(s10[0], s10[1]));
            pa[1][kb4][1] = ex2h2(pack2(s10[2], s10[3]));
            pa[1][kb4][2] = ex2h2(pack2(s11[0], s11[1]));
            pa[1][kb4][3] = ex2h2(pack2(s11[2], s11[3]));
            mma16816(lacc[0], pa[0][kb4], ONESH2, ONESH2);
            mma16816(lacc[1], pa[1][kb4], ONESH2, ONESH2);
        }

        // ---- O += P V^T (f16 accumulate) ----
        #pragma unroll
        for (int kb4 = 0; kb4 < 4; ++kb4) {
            #pragma unroll
            for (int cb = 0; cb < 8; ++cb) {
                uint32_t vf[4];
                ldsm4(vf, vb + cb * 16 * VROW + ro_v + kb4 * 32);
                mma16816h(oacc[0][2 * cb],     pa[0][kb4], vf[0], vf[2]);
                mma16816h(oacc[0][2 * cb + 1], pa[0][kb4], vf[1], vf[3]);
                mma16816h(oacc[1][2 * cb],     pa[1][kb4], vf[0], vf[2]);
                mma16816h(oacc[1][2 * cb + 1], pa[1][kb4], vf[1], vf[3]);
            }
        }

        if (j + 2 < 16) load_kv(j + 2, (j + 2) % 3);
    }

    // ---- epilogue: O / l -> oT[b][n][c] (fp32 scaling) ----
    const int fr = lane >> 2, fc = (lane & 3) * 2;
    ht* Ob = O + (size_t)b * (NSP * NCH) + (size_t)(q0 + wid * 32) * NCH + h * 128;
    #pragma unroll
    for (int mb = 0; mb < 2; ++mb) {
        const float i0 = 1.f / lacc[mb][0], i1 = 1.f / lacc[mb][2];
        ht* Or0 = Ob + (size_t)(mb * 16 + fr) * NCH;
        ht* Or1 = Ob + (size_t)(mb * 16 + fr + 8) * NCH;
        #pragma unroll
        for (int jn = 0; jn < 16; ++jn) {
            float2 f0 = __half22float2(*(__half2*)&oacc[mb][jn][0]);
            float2 f1 = __half22float2(*(__half2*)&oacc[mb][jn][1]);
            *(__half2*)(Or0 + jn * 8 + fc) = __floats2half2_rn(f0.x * i0, f0.y * i0);
            *(__half2*)(Or1 + jn * 8 + fc) = __floats2half2_rn(f1.x * i1, f1.y * i1);
        }
    }
}

// ------------------------------ launch ---------------------------------------
extern "C" void kernel_launch(void* const* d_in, const int* in_sizes, int n_in,
                              void* d_out, int out_size) {
    const float* x      = (const float*)d_in[0];
    const float* gamma  = (const float*)d_in[1];
    const float* beta   = (const float*)d_in[2];
    const float* w_qkv  = (const float*)d_in[3];
    const float* b_qkv  = (const float*)d_in[4];
    const float* w_proj = (const float*)d_in[5];
    const float* b_proj = (const float*)d_in[6];
    float* out = (float*)d_out;

    ht *xn, *wq, *wp, *qk, *v, *oT;
    cudaGetSymbolAddress((void**)&xn, g_xn);
    cudaGetSymbolAddress((void**)&wq, g_wq);
    cudaGetSymbolAddress((void**)&wp, g_wp);
    cudaGetSymbolAddress((void**)&qk, g_qk);
    cudaGetSymbolAddress((void**)&v,  g_v);
    cudaGetSymbolAddress((void**)&oT, g_oT);

    cudaFuncSetAttribute(gemm_mma<0>, cudaFuncAttributeMaxDynamicSharedMemorySize, SMEMSZ);
    cudaFuncSetAttribute(gemm_mma<3>, cudaFuncAttributeMaxDynamicSharedMemorySize, SMEMSZ);
    cudaFuncSetAttribute(flash_kernel, cudaFuncAttributeMaxDynamicSharedMemorySize, FSMEM);

    // groupnorm (512 blocks) + weight convert (4096 blocks) in one launch
    prep_kernel<<<4608, 256>>>(x, gamma, beta, xn, w_qkv, w_proj, wq, wp);

    // QKV: q/k -> qkT (transposed, q pre-scaled), v -> [b][c][m]
    gemm_mma<0><<<dim3(8, 12, NB), 128, SMEMSZ>>>(
        wq, xn, nullptr, qk, v, b_qkv, nullptr);
    // fused S + softmax + O -> oT
    flash_kernel<<<dim3(8, 64), 128, FSMEM>>>(qk, v, oT);
    // out = x + w_proj O + b_proj
    gemm_mma<3><<<dim3(8, 4, NB), 128, SMEMSZ>>>(
        wp, oT, out, nullptr, nullptr, b_proj, x);
}

// round 15
// speedup vs baseline: 1.2308x; 1.0458x over previous
#include <cuda_runtime.h>
#include <cuda_fp16.h>
#include <cstdint>
#include <math.h>

typedef __half ht;

#define NCH  512
#define NSP  1024
#define NB   16
#define CHN  (NCH*NSP)
#define QS   0.08838834764831845f
#define QSE  (0.08838834764831845f * 1.4426950408889634f)   // fold log2(e) for exp2

// --------------------------- scratch (device globals) ------------------------
__device__ ht g_xn [(size_t)NB*NSP*NCH];      // [b][n][c]
__device__ ht g_wq [1536*512];
__device__ ht g_wp [512*512];
__device__ ht g_qk [(size_t)NB*NSP*1024];     // [b][n][q(512)|k(512)]
__device__ ht g_v  [(size_t)NB*NCH*NSP];      // [b][c][m]
__device__ ht g_oT [(size_t)NB*NSP*NCH];      // [b][n][c]

// ------------------------------ PTX helpers ----------------------------------
__device__ __forceinline__ uint32_t smem_u32(const void* p) {
    uint32_t a;
    asm("{ .reg .u64 t; cvta.to.shared.u64 t, %1; cvt.u32.u64 %0, t; }" : "=r"(a) : "l"(p));
    return a;
}
__device__ __forceinline__ void ldsm4(uint32_t* r, uint32_t addr) {
    asm volatile("ldmatrix.sync.aligned.m8n8.x4.shared.b16 {%0,%1,%2,%3}, [%4];"
        : "=r"(r[0]), "=r"(r[1]), "=r"(r[2]), "=r"(r[3]) : "r"(addr));
}
__device__ __forceinline__ void mma16816(float* d, const uint32_t* a, uint32_t b0, uint32_t b1) {
    asm volatile("mma.sync.aligned.m16n8k16.row.col.f32.f16.f16.f32 "
        "{%0,%1,%2,%3}, {%4,%5,%6,%7}, {%8,%9}, {%0,%1,%2,%3};"
        : "+f"(d[0]), "+f"(d[1]), "+f"(d[2]), "+f"(d[3])
        : "r"(a[0]), "r"(a[1]), "r"(a[2]), "r"(a[3]), "r"(b0), "r"(b1));
}
__device__ __forceinline__ void mma16816h(uint32_t* d, const uint32_t* a, uint32_t b0, uint32_t b1) {
    asm volatile("mma.sync.aligned.m16n8k16.row.col.f16.f16.f16.f16 "
        "{%0,%1}, {%2,%3,%4,%5}, {%6,%7}, {%0,%1};"
        : "+r"(d[0]), "+r"(d[1])
        : "r"(a[0]), "r"(a[1]), "r"(a[2]), "r"(a[3]), "r"(b0), "r"(b1));
}
__device__ __forceinline__ uint32_t ex2h2(uint32_t x) {
    uint32_t y;
    asm("ex2.approx.f16x2 %0, %1;" : "=r"(y) : "r"(x));
    return y;
}
#define CP_ASYNC(dst, src) asm volatile("cp.async.cg.shared.global [%0], [%1], 16;" :: "r"(dst), "l"(src))
#define CP_COMMIT()  asm volatile("cp.async.commit_group;" ::: "memory")
#define CP_WAIT1()   asm volatile("cp.async.wait_group 1;" ::: "memory")
#define CP_WAIT0()   asm volatile("cp.async.wait_group 0;" ::: "memory")

// ----------------- prep: groupnorm (blocks 0..511) + weight convert ----------
__global__ __launch_bounds__(256)
void prep_kernel(const float* __restrict__ x, const float* __restrict__ gamma,
                 const float* __restrict__ beta, ht* __restrict__ xn,
                 const float* __restrict__ wq, const float* __restrict__ wp,
                 ht* __restrict__ wqo, ht* __restrict__ wpo) {
    if (blockIdx.x >= 512) {
        int i = (blockIdx.x - 512) * 256 + threadIdx.x;
        if (i < 1536*512) {
            float v = wq[i];
            if (i < 512*512) v *= QSE;            // fold (1/sqrt(hd))*log2(e) into w_q
            wqo[i] = __float2half_rn(v);
        } else {
            int j = i - 1536*512;
            if (j < 512*512) wpo[j] = __float2half_rn(wp[j]);
        }
        return;
    }
    const int b = blockIdx.x >> 5, g = blockIdx.x & 31;
    const float* xp = x + (size_t)b * CHN + (size_t)g * (16 * NSP);

    float s = 0.f, s2 = 0.f;
    for (int i = threadIdx.x; i < 16 * NSP; i += 256) {
        float v = xp[i]; s += v; s2 += v * v;
    }
    __shared__ float rs[8], rs2[8];
    for (int o = 16; o; o >>= 1) {
        s  += __shfl_xor_sync(0xffffffffu, s,  o);
        s2 += __shfl_xor_sync(0xffffffffu, s2, o);
    }
    int wid = threadIdx.x >> 5;
    if ((threadIdx.x & 31) == 0) { rs[wid] = s; rs2[wid] = s2; }
    __syncthreads();
    s = 0.f; s2 = 0.f;
    #pragma unroll
    for (int i = 0; i < 8; i++) { s += rs[i]; s2 += rs2[i]; }
    const float inv = 1.0f / (16 * NSP);
    float mu = s * inv;
    float rstd = rsqrtf(s2 * inv - mu * mu + 1e-5f);

    const int gc = g * 16;
    for (int n = threadIdx.x; n < NSP; n += 256) {
        union { ht h[16]; uint4 u[2]; } H;
        #pragma unroll
        for (int c = 0; c < 16; ++c) {
            float v = (xp[c * NSP + n] - mu) * rstd * gamma[gc + c] + beta[gc + c];
            H.h[c] = __float2half_rn(v);
        }
        uint4* dh = (uint4*)(xn + (size_t)b * (NSP * NCH) + (size_t)n * NCH + gc);
        dh[0] = H.u[0]; dh[1] = H.u[1];
    }
}

// --------------------------- mma.sync GEMM v4 --------------------------------
// 128 threads, 4 warps as 2(M) x 2(N), warp tile 64x64, CTA tile 128x128.
// K-chunk 64 (NIT=8), 3-stage cp.async ring, ONE __syncthreads per iteration.
// MODE 0: QKV  (z=b) M=1536 N=1024 K=512 : q/k -> qkT transposed, v -> [b][c][m]
// MODE 3: proj (z=b) M=512  N=1024 K=512 : fp32 out (+bias+x)
#define SROW   144         // 64 halfs + 16B pad
#define ATILE  18432       // 128 * 144
#define STAGEB 36864       // A + B
#define NSTAGE 3
#define SMEMSZ (NSTAGE*STAGEB)   // 110592 -> 2 CTAs/SM

template<int MODE>
__global__ __launch_bounds__(128, 2)
void gemm_mma(const ht* __restrict__ Ap, const ht* __restrict__ Bp,
              float* __restrict__ C,
              ht* __restrict__ Oh, ht* __restrict__ Vh,
              const float* __restrict__ bias, const float* __restrict__ resid) {
    extern __shared__ char smem[];
    const uint32_t sbase = smem_u32(smem);
    const int tid = threadIdx.x, lane = tid & 31, wid = tid >> 5;
    const int wm = wid >> 1, wn = wid & 1;       // 2 warps M, 2 warps N
    const int m_w = wm * 64, n_w = wn * 64;
    const int z = blockIdx.z, m0 = blockIdx.y * 128, n0 = blockIdx.x * 128;

    const int lda = 512, ldb = 512, Ktot = 512;
    const size_t aoff = (size_t)m0 * 512;
    const size_t boff = (size_t)z * (NSP * NCH) + (size_t)n0 * 512;

    float acc[4][8][4] = {};
    const int NIT = Ktot / 64;    // 8

    // 2048 16B-chunks/stage (A 1024 + B 1024), 16 per thread
    auto load_stage = [&](int it, int s) {
        const int k0 = it * 64;
        const uint32_t sb = sbase + s * STAGEB;
        #pragma unroll
        for (int i = 0; i < 16; ++i) {
            int c = tid + i * 128;
            int row = (c >> 3) & 127, col = c & 7;
            if (i < 8) {
                CP_ASYNC(sb + row * SROW + col * 16,
                         Ap + aoff + (size_t)row * lda + k0 + col * 8);
            } else {
                CP_ASYNC(sb + ATILE + row * SROW + col * 16,
                         Bp + boff + (size_t)row * ldb + k0 + col * 8);
            }
        }
        CP_COMMIT();
    };

    load_stage(0, 0); load_stage(1, 1);

    for (int it = 0; it < NIT; ++it) {
        const int s = it % 3;
        if (it + 1 < NIT) { CP_WAIT1(); } else { CP_WAIT0(); }
        __syncthreads();

        const uint32_t ab = sbase + s * STAGEB;
        const uint32_t rofs = (lane & 15) * SROW + ((lane >> 4) << 4);
        #pragma unroll
        for (int k16 = 0; k16 < 4; ++k16) {
            const uint32_t ko = k16 * 32 + rofs;
            uint32_t bfr[4][4];
            #pragma unroll
            for (int j = 0; j < 4; ++j)
                ldsm4(bfr[j], ab + ATILE + (n_w + j * 16) * SROW + ko);
            uint32_t af[4][4];
            #pragma unroll
            for (int i = 0; i < 4; ++i)
                ldsm4(af[i], ab + (m_w + i * 16) * SROW + ko);
            #pragma unroll
            for (int i = 0; i < 4; ++i)
                #pragma unroll
                for (int jn = 0; jn < 8; ++jn)
                    mma16816(acc[i][jn], af[i],
                             bfr[jn >> 1][jn & 1], bfr[jn >> 1][(jn & 1) + 2]);
        }
        if (it + 2 < NIT) load_stage(it + 2, (it + 2) % 3);
    }

    const int fr = lane >> 2;
    const int fc = (lane & 3) * 2;

    if (MODE == 3) {
        #pragma unroll
        for (int i = 0; i < 4; ++i)
            #pragma unroll
            for (int jn = 0; jn < 8; ++jn)
                #pragma unroll
                for (int rh = 0; rh < 2; ++rh) {
                    int row = m0 + m_w + i * 16 + fr + rh * 8;
                    int col = n0 + n_w + jn * 8 + fc;
                    float bv = bias[row];
                    const float2 xv = *(const float2*)(resid + (size_t)z * CHN + (size_t)row * NSP + col);
                    *(float2*)(C + (size_t)z * CHN + (size_t)row * NSP + col) =
                        make_float2(acc[i][jn][rh * 2] + bv + xv.x,
                                    acc[i][jn][rh * 2 + 1] + bv + xv.y);
                }
    } else if (MODE == 0 && m0 >= 1024) {
        // V region: [b][c][m]
        #pragma unroll
        for (int i = 0; i < 4; ++i)
            #pragma unroll
            for (int jn = 0; jn < 8; ++jn)
                #pragma unroll
                for (int rh = 0; rh < 2; ++rh) {
                    int mi = m_w + i * 16 + fr + rh * 8;
                    float bv = bias[m0 + mi];
                    int cc2 = m0 - 1024 + mi;
                    size_t off = (size_t)z * (NCH * NSP) + (size_t)cc2 * NSP + n0 + n_w + jn * 8 + fc;
                    *(__half2*)(Vh + off) = __halves2half2(
                        __float2half_rn(acc[i][jn][rh * 2] + bv),
                        __float2half_rn(acc[i][jn][rh * 2 + 1] + bv));
                }
    } else {
        // q/k region -> transposed qkT; two n-halves of 64
        uint32_t* TB = (uint32_t*)smem;       // [64 n][132 m]
        #pragma unroll
        for (int hh = 0; hh < 2; ++hh) {
            __syncthreads();
            if (wn == hh) {
                #pragma unroll
                for (int i = 0; i < 4; ++i)
                    #pragma unroll
                    for (int jn = 0; jn < 8; ++jn)
                        #pragma unroll
                        for (int rh = 0; rh < 2; ++rh) {
                            int mi = m_w + i * 16 + fr + rh * 8;
                            float bv = bias[m0 + mi];
                            if (m0 < 512) bv *= QSE;
                            float v0 = acc[i][jn][rh * 2] + bv;
                            float v1 = acc[i][jn][rh * 2 + 1] + bv;
                            int ncl = jn * 8 + fc;
                            TB[ncl * 132 + mi]       = (uint32_t)__half_as_ushort(__float2half_rn(v0));
                            TB[(ncl + 1) * 132 + mi] = (uint32_t)__half_as_ushort(__float2half_rn(v1));
                        }
            }
            __syncthreads();
            int rr = tid >> 1, seg = (tid & 1) * 64;
            size_t nco = (size_t)z * (NSP * 1024) + (size_t)(n0 + hh * 64 + rr) * 1024 + m0 + seg;
            #pragma unroll
            for (int q4 = 0; q4 < 8; ++q4) {
                union { ht h[8]; uint4 u; } H;
                #pragma unroll
                for (int e = 0; e < 8; ++e)
                    H.h[e] = __ushort_as_half((unsigned short)(TB[rr * 132 + seg + q4 * 8 + e] & 0xffffu));
                *(uint4*)(Oh + nco + q4 * 8) = H.u;
            }
        }
    }
}

// ------------------------- flash attention v6 --------------------------------
// 128 threads (4 warps), q-tile 128 (32 q rows/warp), kv-chunk 64, 2 CTAs/SM.
// 3-stage KV ring; Q overlays stage 2. S-MMA uses f16 accumulators (output is
// already in packed half2 A-fragment layout -> ex2h2 directly, no pack/cvt).
#define KROW  272                  // 128 halfs + 16B pad
#define VROW  144                  // 64 halfs + 16B pad
#define KTILE (64*KROW)            // 17408
#define VTILE (128*VROW)           // 18432
#define FSTG  (KTILE+VTILE)        // 35840
#define FSMEM (3*FSTG)             // 107520
#define QOFF  (2*FSTG)             // Q tile overlays stage 2
#define ONESH2 0x3C003C00u

__global__ __launch_bounds__(128, 2)
void flash_kernel(const ht* __restrict__ QK, const ht* __restrict__ Vg_,
                  ht* __restrict__ O) {
    extern __shared__ char smem[];
    const uint32_t sbase = smem_u32(smem);
    const int tid = threadIdx.x, lane = tid & 31, wid = tid >> 5;
    const int z = blockIdx.y, b = z >> 2, h = z & 3;
    const int q0 = blockIdx.x * 128;

    const ht* Qg = QK  + (size_t)b * (NSP * 1024) + (size_t)q0 * 1024 + h * 128;
    const ht* Kg = QK  + (size_t)b * (NSP * 1024) + 512 + h * 128;
    const ht* Vg = Vg_ + (size_t)b * CHN + (size_t)(h * 128) * NSP;

    auto load_kv = [&](int j, int s) {
        const uint32_t kb = sbase + s * FSTG;
        const uint32_t vb = kb + KTILE;
        #pragma unroll
        for (int i = 0; i < 8; ++i) {           // K: 64 rows x 128 halfs
            int c = tid + i * 128;
            int row = c >> 4, col = c & 15;
            CP_ASYNC(kb + row * KROW + col * 16, Kg + (size_t)(j * 64 + row) * 1024 + col * 8);
        }
        #pragma unroll
        for (int i = 0; i < 8; ++i) {           // V: 128 rows x 64 halfs
            int c = tid + i * 128;
            int row = c >> 3, col = c & 7;
            CP_ASYNC(vb + row * VROW + col * 16, Vg + (size_t)row * NSP + j * 64 + col * 8);
        }
        CP_COMMIT();
    };

    // Q tile -> QOFF (group 1)
    #pragma unroll
    for (int i = 0; i < 16; ++i) {
        int c = tid + i * 128;
        int row = c >> 4, col = c & 15;
        CP_ASYNC(sbase + QOFF + row * KROW + col * 16, Qg + (size_t)row * 1024 + col * 8);
    }
    CP_COMMIT();
    load_kv(0, 0);                 // group 2
    load_kv(1, 1);                 // group 3
    CP_WAIT1();                    // Q + KV0 complete
    __syncthreads();

    // Q fragments: warp owns q rows [wid*32, wid*32+32) -> 2 m-blocks
    uint32_t qf[2][8][4];
    #pragma unroll
    for (int mb = 0; mb < 2; ++mb) {
        const uint32_t base = sbase + QOFF + (wid * 32 + mb * 16 + (lane & 15)) * KROW
                            + ((lane >> 4) << 4);
        #pragma unroll
        for (int k16 = 0; k16 < 8; ++k16) ldsm4(qf[mb][k16], base + k16 * 32);
    }

    uint32_t oacc[2][16][2] = {};    // f16 accumulators: [mb][n8(ch)][reg]
    float lacc[2][4] = {};           // row sums via ones-MMA (fp32)

    const uint32_t ro_k = (lane & 15) * KROW + ((lane >> 4) << 4);
    const uint32_t ro_v = (lane & 15) * VROW + ((lane >> 4) << 4);

    for (int j = 0; j < 16; ++j) {
        const int s = j % 3;
        if (j + 1 < 16) { CP_WAIT1(); } else { CP_WAIT0(); }
        __syncthreads();            // stage s visible; also fences Q reads (j==0)

        const uint32_t kb = sbase + s * FSTG;
        const uint32_t vb = kb + KTILE;

        // ---- S = Q K^T (f16 acc) per 16-kv block -> exp2 -> P fragments ----
        uint32_t pa[2][4][4];        // [mb][kb4][reg]
        #pragma unroll
        for (int kb4 = 0; kb4 < 4; ++kb4) {
            uint32_t s00[2] = {}, s01[2] = {}, s10[2] = {}, s11[2] = {};
            const uint32_t base = kb + kb4 * 16 * KROW + ro_k;
            #pragma unroll
            for (int k16 = 0; k16 < 8; ++k16) {
                uint32_t bf[4];
                ldsm4(bf, base + k16 * 32);
                mma16816h(s00, qf[0][k16], bf[0], bf[2]);
                mma16816h(s01, qf[0][k16], bf[1], bf[3]);
                mma16816h(s10, qf[1][k16], bf[0], bf[2]);
                mma16816h(s11, qf[1][k16], bf[1], bf[3]);
            }
            pa[0][kb4][0] = ex2h2(s00[0]);
            pa[0][kb4][1] = ex2h2(s00[1]);
            pa[0][kb4][2] = ex2h2(s01[0]);
            pa[0][kb4][3] = ex2h2(s01[1]);
            pa[1][kb4][0] = ex2h2(s10[0]);
            pa[1][kb4][1] = ex2h2(s10[1]);
            pa[1][kb4][2] = ex2h2(s11[0]);
            pa[1][kb4][3] = ex2h2(s11[1]);
            mma16816(lacc[0], pa[0][kb4], ONESH2, ONESH2);
            mma16816(lacc[1], pa[1][kb4], ONESH2, ONESH2);
        }

        // ---- O += P V^T (f16 accumulate) ----
        #pragma unroll
        for (int kb4 = 0; kb4 < 4; ++kb4) {
            #pragma unroll
            for (int cb = 0; cb < 8; ++cb) {
                uint32_t vf[4];
                ldsm4(vf, vb + cb * 16 * VROW + ro_v + kb4 * 32);
                mma16816h(oacc[0][2 * cb],     pa[0][kb4], vf[0], vf[2]);
                mma16816h(oacc[0][2 * cb + 1], pa[0][kb4], vf[1], vf[3]);
                mma16816h(oacc[1][2 * cb],     pa[1][kb4], vf[0], vf[2]);
                mma16816h(oacc[1][2 * cb + 1], pa[1][kb4], vf[1], vf[3]);
            }
        }

        if (j + 2 < 16) load_kv(j + 2, (j + 2) % 3);
    }

    // ---- epilogue: O / l -> oT[b][n][c] (fp32 scaling) ----
    const int fr = lane >> 2, fc = (lane & 3) * 2;
    ht* Ob = O + (size_t)b * (NSP * NCH) + (size_t)(q0 + wid * 32) * NCH + h * 128;
    #pragma unroll
    for (int mb = 0; mb < 2; ++mb) {
        const float i0 = 1.f / lacc[mb][0], i1 = 1.f / lacc[mb][2];
        ht* Or0 = Ob + (size_t)(mb * 16 + fr) * NCH;
        ht* Or1 = Ob + (size_t)(mb * 16 + fr + 8) * NCH;
        #pragma unroll
        for (int jn = 0; jn < 16; ++jn) {
            float2 f0 = __half22float2(*(__half2*)&oacc[mb][jn][0]);
            float2 f1 = __half22float2(*(__half2*)&oacc[mb][jn][1]);
            *(__half2*)(Or0 + jn * 8 + fc) = __floats2half2_rn(f0.x * i0, f0.y * i0);
            *(__half2*)(Or1 + jn * 8 + fc) = __floats2half2_rn(f1.x * i1, f1.y * i1);
        }
    }
}

// ------------------------------ launch ---------------------------------------
extern "C" void kernel_launch(void* const* d_in, const int* in_sizes, int n_in,
                              void* d_out, int out_size) {
    const float* x      = (const float*)d_in[0];
    const float* gamma  = (const float*)d_in[1];
    const float* beta   = (const float*)d_in[2];
    const float* w_qkv  = (const float*)d_in[3];
    const float* b_qkv  = (const float*)d_in[4];
    const float* w_proj = (const float*)d_in[5];
    const float* b_proj = (const float*)d_in[6];
    float* out = (float*)d_out;

    ht *xn, *wq, *wp, *qk, *v, *oT;
    cudaGetSymbolAddress((void**)&xn, g_xn);
    cudaGetSymbolAddress((void**)&wq, g_wq);
    cudaGetSymbolAddress((void**)&wp, g_wp);
    cudaGetSymbolAddress((void**)&qk, g_qk);
    cudaGetSymbolAddress((void**)&v,  g_v);
    cudaGetSymbolAddress((void**)&oT, g_oT);

    cudaFuncSetAttribute(gemm_mma<0>, cudaFuncAttributeMaxDynamicSharedMemorySize, SMEMSZ);
    cudaFuncSetAttribute(gemm_mma<3>, cudaFuncAttributeMaxDynamicSharedMemorySize, SMEMSZ);
    cudaFuncSetAttribute(flash_kernel, cudaFuncAttributeMaxDynamicSharedMemorySize, FSMEM);

    // groupnorm (512 blocks) + weight convert (4096 blocks) in one launch
    prep_kernel<<<4608, 256>>>(x, gamma, beta, xn, w_qkv, w_proj, wq, wp);

    // QKV: q/k -> qkT (transposed, q pre-scaled), v -> [b][c][m]
    gemm_mma<0><<<dim3(8, 12, NB), 128, SMEMSZ>>>(
        wq, xn, nullptr, qk, v, b_qkv, nullptr);
    // fused S + softmax + O -> oT
    flash_kernel<<<dim3(8, 64), 128, FSMEM>>>(qk, v, oT);
    // out = x + w_proj O + b_proj
    gemm_mma<3><<<dim3(8, 4, NB), 128, SMEMSZ>>>(
        wp, oT, out, nullptr, nullptr, b_proj, x);
}

// round 16
// speedup vs baseline: 1.2334x; 1.0021x over previous
#include <cuda_runtime.h>
#include <cuda_fp16.h>
#include <cstdint>
#include <math.h>

typedef __half ht;

#define NCH  512
#define NSP  1024
#define NB   16
#define CHN  (NCH*NSP)
#define QS   0.08838834764831845f
#define QSE  (0.08838834764831845f * 1.4426950408889634f)   // fold log2(e) for exp2

// --------------------------- scratch (device globals) ------------------------
__device__ ht g_xn [(size_t)NB*NSP*NCH];      // [b][n][c]
__device__ ht g_wq [1536*512];
__device__ ht g_wp [512*512];
__device__ ht g_qk [(size_t)NB*NSP*1024];     // [b][n][q(512)|k(512)]
__device__ ht g_v  [(size_t)NB*NCH*NSP];      // [b][c][m]
__device__ ht g_oT [(size_t)NB*NSP*NCH];      // [b][n][c]

// ------------------------------ PTX helpers ----------------------------------
__device__ __forceinline__ uint32_t smem_u32(const void* p) {
    uint32_t a;
    asm("{ .reg .u64 t; cvta.to.shared.u64 t, %1; cvt.u32.u64 %0, t; }" : "=r"(a) : "l"(p));
    return a;
}
__device__ __forceinline__ void ldsm4(uint32_t* r, uint32_t addr) {
    asm volatile("ldmatrix.sync.aligned.m8n8.x4.shared.b16 {%0,%1,%2,%3}, [%4];"
        : "=r"(r[0]), "=r"(r[1]), "=r"(r[2]), "=r"(r[3]) : "r"(addr));
}
__device__ __forceinline__ void mma16816(float* d, const uint32_t* a, uint32_t b0, uint32_t b1) {
    asm volatile("mma.sync.aligned.m16n8k16.row.col.f32.f16.f16.f32 "
        "{%0,%1,%2,%3}, {%4,%5,%6,%7}, {%8,%9}, {%0,%1,%2,%3};"
        : "+f"(d[0]), "+f"(d[1]), "+f"(d[2]), "+f"(d[3])
        : "r"(a[0]), "r"(a[1]), "r"(a[2]), "r"(a[3]), "r"(b0), "r"(b1));
}
__device__ __forceinline__ void mma16816h(uint32_t* d, const uint32_t* a, uint32_t b0, uint32_t b1) {
    asm volatile("mma.sync.aligned.m16n8k16.row.col.f16.f16.f16.f16 "
        "{%0,%1}, {%2,%3,%4,%5}, {%6,%7}, {%0,%1};"
        : "+r"(d[0]), "+r"(d[1])
        : "r"(a[0]), "r"(a[1]), "r"(a[2]), "r"(a[3]), "r"(b0), "r"(b1));
}
__device__ __forceinline__ uint32_t ex2h2(uint32_t x) {
    uint32_t y;
    asm("ex2.approx.f16x2 %0, %1;" : "=r"(y) : "r"(x));
    return y;
}
#define CP_ASYNC(dst, src) asm volatile("cp.async.cg.shared.global [%0], [%1], 16;" :: "r"(dst), "l"(src))
#define CP_COMMIT()  asm volatile("cp.async.commit_group;" ::: "memory")
#define CP_WAIT1()   asm volatile("cp.async.wait_group 1;" ::: "memory")
#define CP_WAIT0()   asm volatile("cp.async.wait_group 0;" ::: "memory")

// ----------------- prep: groupnorm (blocks 0..511) + weight convert ----------
__global__ __launch_bounds__(256)
void prep_kernel(const float* __restrict__ x, const float* __restrict__ gamma,
                 const float* __restrict__ beta, ht* __restrict__ xn,
                 const float* __restrict__ wq, const float* __restrict__ wp,
                 ht* __restrict__ wqo, ht* __restrict__ wpo) {
    if (blockIdx.x >= 512) {
        int i = (blockIdx.x - 512) * 256 + threadIdx.x;
        if (i < 1536*512) {
            float v = wq[i];
            if (i < 512*512) v *= QSE;            // fold (1/sqrt(hd))*log2(e) into w_q
            wqo[i] = __float2half_rn(v);
        } else {
            int j = i - 1536*512;
            if (j < 512*512) wpo[j] = __float2half_rn(wp[j]);
        }
        return;
    }
    const int b = blockIdx.x >> 5, g = blockIdx.x & 31;
    const float* xp = x + (size_t)b * CHN + (size_t)g * (16 * NSP);

    float s = 0.f, s2 = 0.f;
    for (int i = threadIdx.x; i < 16 * NSP; i += 256) {
        float v = xp[i]; s += v; s2 += v * v;
    }
    __shared__ float rs[8], rs2[8];
    for (int o = 16; o; o >>= 1) {
        s  += __shfl_xor_sync(0xffffffffu, s,  o);
        s2 += __shfl_xor_sync(0xffffffffu, s2, o);
    }
    int wid = threadIdx.x >> 5;
    if ((threadIdx.x & 31) == 0) { rs[wid] = s; rs2[wid] = s2; }
    __syncthreads();
    s = 0.f; s2 = 0.f;
    #pragma unroll
    for (int i = 0; i < 8; i++) { s += rs[i]; s2 += rs2[i]; }
    const float inv = 1.0f / (16 * NSP);
    float mu = s * inv;
    float rstd = rsqrtf(s2 * inv - mu * mu + 1e-5f);

    const int gc = g * 16;
    for (int n = threadIdx.x; n < NSP; n += 256) {
        union { ht h[16]; uint4 u[2]; } H;
        #pragma unroll
        for (int c = 0; c < 16; ++c) {
            float v = (xp[c * NSP + n] - mu) * rstd * gamma[gc + c] + beta[gc + c];
            H.h[c] = __float2half_rn(v);
        }
        uint4* dh = (uint4*)(xn + (size_t)b * (NSP * NCH) + (size_t)n * NCH + gc);
        dh[0] = H.u[0]; dh[1] = H.u[1];
    }
}

// --------------------------- mma.sync GEMM v5 --------------------------------
// 256 threads, 8 warps as 2(M) x 4(N), warp tile 64x32, CTA tile 128x128.
// K-chunk 64 (NIT=8), 3-stage ring, ONE barrier/iter. 16 warps/SM (2 CTAs).
// MODE 0: QKV  (z=b) M=1536 N=1024 K=512 : q/k -> qkT transposed, v -> [b][c][m]
// MODE 3: proj (z=b) M=512  N=1024 K=512 : fp32 out (+bias+x)
#define SROW   144         // 64 halfs + 16B pad
#define ATILE  18432       // 128 * 144
#define STAGEB 36864       // A + B
#define NSTAGE 3
#define SMEMSZ (NSTAGE*STAGEB)   // 110592 -> 2 CTAs/SM by smem

template<int MODE>
__global__ __launch_bounds__(256, 2)
void gemm_mma(const ht* __restrict__ Ap, const ht* __restrict__ Bp,
              float* __restrict__ C,
              ht* __restrict__ Oh, ht* __restrict__ Vh,
              const float* __restrict__ bias, const float* __restrict__ resid) {
    extern __shared__ char smem[];
    const uint32_t sbase = smem_u32(smem);
    const int tid = threadIdx.x, lane = tid & 31, wid = tid >> 5;
    const int wm = wid >> 2, wn = wid & 3;       // 2 warps M, 4 warps N
    const int m_w = wm * 64, n_w = wn * 32;
    const int z = blockIdx.z, m0 = blockIdx.y * 128, n0 = blockIdx.x * 128;

    const int lda = 512, ldb = 512, Ktot = 512;
    const size_t aoff = (size_t)m0 * 512;
    const size_t boff = (size_t)z * (NSP * NCH) + (size_t)n0 * 512;

    float acc[4][4][4] = {};      // [m16][n8][frag]
    const int NIT = Ktot / 64;    // 8

    // 2048 16B-chunks/stage (A 1024 + B 1024), 8 per thread
    auto load_stage = [&](int it, int s) {
        const int k0 = it * 64;
        const uint32_t sb = sbase + s * STAGEB;
        #pragma unroll
        for (int i = 0; i < 8; ++i) {
            int c = tid + i * 256;
            int row = (c >> 3) & 127, col = c & 7;
            if (i < 4) {
                CP_ASYNC(sb + row * SROW + col * 16,
                         Ap + aoff + (size_t)row * lda + k0 + col * 8);
            } else {
                CP_ASYNC(sb + ATILE + row * SROW + col * 16,
                         Bp + boff + (size_t)row * ldb + k0 + col * 8);
            }
        }
        CP_COMMIT();
    };

    load_stage(0, 0); load_stage(1, 1);

    for (int it = 0; it < NIT; ++it) {
        const int s = it % 3;
        if (it + 1 < NIT) { CP_WAIT1(); } else { CP_WAIT0(); }
        __syncthreads();

        const uint32_t ab = sbase + s * STAGEB;
        const uint32_t rofs = (lane & 15) * SROW + ((lane >> 4) << 4);
        #pragma unroll
        for (int k16 = 0; k16 < 4; ++k16) {
            const uint32_t ko = k16 * 32 + rofs;
            uint32_t bfr[2][4];
            #pragma unroll
            for (int j = 0; j < 2; ++j)
                ldsm4(bfr[j], ab + ATILE + (n_w + j * 16) * SROW + ko);
            uint32_t af[4][4];
            #pragma unroll
            for (int i = 0; i < 4; ++i)
                ldsm4(af[i], ab + (m_w + i * 16) * SROW + ko);
            #pragma unroll
            for (int i = 0; i < 4; ++i)
                #pragma unroll
                for (int jn = 0; jn < 4; ++jn)
                    mma16816(acc[i][jn], af[i],
                             bfr[jn >> 1][jn & 1], bfr[jn >> 1][(jn & 1) + 2]);
        }
        if (it + 2 < NIT) load_stage(it + 2, (it + 2) % 3);
    }

    const int fr = lane >> 2;
    const int fc = (lane & 3) * 2;

    if (MODE == 3) {
        #pragma unroll
        for (int i = 0; i < 4; ++i)
            #pragma unroll
            for (int jn = 0; jn < 4; ++jn)
                #pragma unroll
                for (int rh = 0; rh < 2; ++rh) {
                    int row = m0 + m_w + i * 16 + fr + rh * 8;
                    int col = n0 + n_w + jn * 8 + fc;
                    float bv = bias[row];
                    const float2 xv = *(const float2*)(resid + (size_t)z * CHN + (size_t)row * NSP + col);
                    *(float2*)(C + (size_t)z * CHN + (size_t)row * NSP + col) =
                        make_float2(acc[i][jn][rh * 2] + bv + xv.x,
                                    acc[i][jn][rh * 2 + 1] + bv + xv.y);
                }
    } else if (MODE == 0 && m0 >= 1024) {
        // V region: [b][c][m]
        #pragma unroll
        for (int i = 0; i < 4; ++i)
            #pragma unroll
            for (int jn = 0; jn < 4; ++jn)
                #pragma unroll
                for (int rh = 0; rh < 2; ++rh) {
                    int mi = m_w + i * 16 + fr + rh * 8;
                    float bv = bias[m0 + mi];
                    int cc2 = m0 - 1024 + mi;
                    size_t off = (size_t)z * (NCH * NSP) + (size_t)cc2 * NSP + n0 + n_w + jn * 8 + fc;
                    *(__half2*)(Vh + off) = __halves2half2(
                        __float2half_rn(acc[i][jn][rh * 2] + bv),
                        __float2half_rn(acc[i][jn][rh * 2 + 1] + bv));
                }
    } else {
        // q/k region -> transposed qkT; two n-halves of 64 (warps wn>>1 == hh)
        uint32_t* TB = (uint32_t*)smem;       // [64 n][132 m]
        #pragma unroll
        for (int hh = 0; hh < 2; ++hh) {
            __syncthreads();
            if ((wn >> 1) == hh) {
                #pragma unroll
                for (int i = 0; i < 4; ++i)
                    #pragma unroll
                    for (int jn = 0; jn < 4; ++jn)
                        #pragma unroll
                        for (int rh = 0; rh < 2; ++rh) {
                            int mi = m_w + i * 16 + fr + rh * 8;
                            float bv = bias[m0 + mi];
                            if (m0 < 512) bv *= QSE;
                            float v0 = acc[i][jn][rh * 2] + bv;
                            float v1 = acc[i][jn][rh * 2 + 1] + bv;
                            int ncl = (wn & 1) * 32 + jn * 8 + fc;
                            TB[ncl * 132 + mi]       = (uint32_t)__half_as_ushort(__float2half_rn(v0));
                            TB[(ncl + 1) * 132 + mi] = (uint32_t)__half_as_ushort(__float2half_rn(v1));
                        }
            }
            __syncthreads();
            int rr = tid >> 2, seg = (tid & 3) * 32;
            size_t nco = (size_t)z * (NSP * 1024) + (size_t)(n0 + hh * 64 + rr) * 1024 + m0 + seg;
            #pragma unroll
            for (int q4 = 0; q4 < 4; ++q4) {
                union { ht h[8]; uint4 u; } H;
                #pragma unroll
                for (int e = 0; e < 8; ++e)
                    H.h[e] = __ushort_as_half((unsigned short)(TB[rr * 132 + seg + q4 * 8 + e] & 0xffffu));
                *(uint4*)(Oh + nco + q4 * 8) = H.u;
            }
        }
    }
}

// ------------------------- flash attention v6 (R15) --------------------------
// 128 threads (4 warps), q-tile 128 (32 q rows/warp), kv-chunk 64, 2 CTAs/SM.
// 3-stage KV ring; Q overlays stage 2. S-MMA f16 acc -> ex2h2 directly.
#define KROW  272                  // 128 halfs + 16B pad
#define VROW  144                  // 64 halfs + 16B pad
#define KTILE (64*KROW)            // 17408
#define VTILE (128*VROW)           // 18432
#define FSTG  (KTILE+VTILE)        // 35840
#define FSMEM (3*FSTG)             // 107520
#define QOFF  (2*FSTG)             // Q tile overlays stage 2
#define ONESH2 0x3C003C00u

__global__ __launch_bounds__(128, 2)
void flash_kernel(const ht* __restrict__ QK, const ht* __restrict__ Vg_,
                  ht* __restrict__ O) {
    extern __shared__ char smem[];
    const uint32_t sbase = smem_u32(smem);
    const int tid = threadIdx.x, lane = tid & 31, wid = tid >> 5;
    const int z = blockIdx.y, b = z >> 2, h = z & 3;
    const int q0 = blockIdx.x * 128;

    const ht* Qg = QK  + (size_t)b * (NSP * 1024) + (size_t)q0 * 1024 + h * 128;
    const ht* Kg = QK  + (size_t)b * (NSP * 1024) + 512 + h * 128;
    const ht* Vg = Vg_ + (size_t)b * CHN + (size_t)(h * 128) * NSP;

    auto load_kv = [&](int j, int s) {
        const uint32_t kb = sbase + s * FSTG;
        const uint32_t vb = kb + KTILE;
        #pragma unroll
        for (int i = 0; i < 8; ++i) {           // K: 64 rows x 128 halfs
            int c = tid + i * 128;
            int row = c >> 4, col = c & 15;
            CP_ASYNC(kb + row * KROW + col * 16, Kg + (size_t)(j * 64 + row) * 1024 + col * 8);
        }
        #pragma unroll
        for (int i = 0; i < 8; ++i) {           // V: 128 rows x 64 halfs
            int c = tid + i * 128;
            int row = c >> 3, col = c & 7;
            CP_ASYNC(vb + row * VROW + col * 16, Vg + (size_t)row * NSP + j * 64 + col * 8);
        }
        CP_COMMIT();
    };

    // Q tile -> QOFF (group 1)
    #pragma unroll
    for (int i = 0; i < 16; ++i) {
        int c = tid + i * 128;
        int row = c >> 4, col = c & 15;
        CP_ASYNC(sbase + QOFF + row * KROW + col * 16, Qg + (size_t)row * 1024 + col * 8);
    }
    CP_COMMIT();
    load_kv(0, 0);                 // group 2
    load_kv(1, 1);                 // group 3
    CP_WAIT1();                    // Q + KV0 complete
    __syncthreads();

    // Q fragments: warp owns q rows [wid*32, wid*32+32) -> 2 m-blocks
    uint32_t qf[2][8][4];
    #pragma unroll
    for (int mb = 0; mb < 2; ++mb) {
        const uint32_t base = sbase + QOFF + (wid * 32 + mb * 16 + (lane & 15)) * KROW
                            + ((lane >> 4) << 4);
        #pragma unroll
        for (int k16 = 0; k16 < 8; ++k16) ldsm4(qf[mb][k16], base + k16 * 32);
    }

    uint32_t oacc[2][16][2] = {};    // f16 accumulators: [mb][n8(ch)][reg]
    float lacc[2][4] = {};           // row sums via ones-MMA (fp32)

    const uint32_t ro_k = (lane & 15) * KROW + ((lane >> 4) << 4);
    const uint32_t ro_v = (lane & 15) * VROW + ((lane >> 4) << 4);

    for (int j = 0; j < 16; ++j) {
        const int s = j % 3;
        if (j + 1 < 16) { CP_WAIT1(); } else { CP_WAIT0(); }
        __syncthreads();            // stage s visible; also fences Q reads (j==0)

        const uint32_t kb = sbase + s * FSTG;
        const uint32_t vb = kb + KTILE;

        // ---- S = Q K^T (f16 acc) per 16-kv block -> exp2 -> P fragments ----
        uint32_t pa[2][4][4];        // [mb][kb4][reg]
        #pragma unroll
        for (int kb4 = 0; kb4 < 4; ++kb4) {
            uint32_t s00[2] = {}, s01[2] = {}, s10[2] = {}, s11[2] = {};
            const uint32_t base = kb + kb4 * 16 * KROW + ro_k;
            #pragma unroll
            for (int k16 = 0; k16 < 8; ++k16) {
                uint32_t bf[4];
                ldsm4(bf, base + k16 * 32);
                mma16816h(s00, qf[0][k16], bf[0], bf[2]);
                mma16816h(s01, qf[0][k16], bf[1], bf[3]);
                mma16816h(s10, qf[1][k16], bf[0], bf[2]);
                mma16816h(s11, qf[1][k16], bf[1], bf[3]);
            }
            pa[0][kb4][0] = ex2h2(s00[0]);
            pa[0][kb4][1] = ex2h2(s00[1]);
            pa[0][kb4][2] = ex2h2(s01[0]);
            pa[0][kb4][3] = ex2h2(s01[1]);
            pa[1][kb4][0] = ex2h2(s10[0]);
            pa[1][kb4][1] = ex2h2(s10[1]);
            pa[1][kb4][2] = ex2h2(s11[0]);
            pa[1][kb4][3] = ex2h2(s11[1]);
            mma16816(lacc[0], pa[0][kb4], ONESH2, ONESH2);
            mma16816(lacc[1], pa[1][kb4], ONESH2, ONESH2);
        }

        // ---- O += P V^T (f16 accumulate) ----
        #pragma unroll
        for (int kb4 = 0; kb4 < 4; ++kb4) {
            #pragma unroll
            for (int cb = 0; cb < 8; ++cb) {
                uint32_t vf[4];
                ldsm4(vf, vb + cb * 16 * VROW + ro_v + kb4 * 32);
                mma16816h(oacc[0][2 * cb],     pa[0][kb4], vf[0], vf[2]);
                mma16816h(oacc[0][2 * cb + 1], pa[0][kb4], vf[1], vf[3]);
                mma16816h(oacc[1][2 * cb],     pa[1][kb4], vf[0], vf[2]);
                mma16816h(oacc[1][2 * cb + 1], pa[1][kb4], vf[1], vf[3]);
            }
        }

        if (j + 2 < 16) load_kv(j + 2, (j + 2) % 3);
    }

    // ---- epilogue: O / l -> oT[b][n][c] (fp32 scaling) ----
    const int fr = lane >> 2, fc = (lane & 3) * 2;
    ht* Ob = O + (size_t)b * (NSP * NCH) + (size_t)(q0 + wid * 32) * NCH + h * 128;
    #pragma unroll
    for (int mb = 0; mb < 2; ++mb) {
        const float i0 = 1.f / lacc[mb][0], i1 = 1.f / lacc[mb][2];
        ht* Or0 = Ob + (size_t)(mb * 16 + fr) * NCH;
        ht* Or1 = Ob + (size_t)(mb * 16 + fr + 8) * NCH;
        #pragma unroll
        for (int jn = 0; jn < 16; ++jn) {
            float2 f0 = __half22float2(*(__half2*)&oacc[mb][jn][0]);
            float2 f1 = __half22float2(*(__half2*)&oacc[mb][jn][1]);
            *(__half2*)(Or0 + jn * 8 + fc) = __floats2half2_rn(f0.x * i0, f0.y * i0);
            *(__half2*)(Or1 + jn * 8 + fc) = __floats2half2_rn(f1.x * i1, f1.y * i1);
        }
    }
}

// ------------------------------ launch ---------------------------------------
extern "C" void kernel_launch(void* const* d_in, const int* in_sizes, int n_in,
                              void* d_out, int out_size) {
    const float* x      = (const float*)d_in[0];
    const float* gamma  = (const float*)d_in[1];
    const float* beta   = (const float*)d_in[2];
    const float* w_qkv  = (const float*)d_in[3];
    const float* b_qkv  = (const float*)d_in[4];
    const float* w_proj = (const float*)d_in[5];
    const float* b_proj = (const float*)d_in[6];
    float* out = (float*)d_out;

    ht *xn, *wq, *wp, *qk, *v, *oT;
    cudaGetSymbolAddress((void**)&xn, g_xn);
    cudaGetSymbolAddress((void**)&wq, g_wq);
    cudaGetSymbolAddress((void**)&wp, g_wp);
    cudaGetSymbolAddress((void**)&qk, g_qk);
    cudaGetSymbolAddress((void**)&v,  g_v);
    cudaGetSymbolAddress((void**)&oT, g_oT);

    cudaFuncSetAttribute(gemm_mma<0>, cudaFuncAttributeMaxDynamicSharedMemorySize, SMEMSZ);
    cudaFuncSetAttribute(gemm_mma<3>, cudaFuncAttributeMaxDynamicSharedMemorySize, SMEMSZ);
    cudaFuncSetAttribute(flash_kernel, cudaFuncAttributeMaxDynamicSharedMemorySize, FSMEM);

    // groupnorm (512 blocks) + weight convert (4096 blocks) in one launch
    prep_kernel<<<4608, 256>>>(x, gamma, beta, xn, w_qkv, w_proj, wq, wp);

    // QKV: q/k -> qkT (transposed, q pre-scaled), v -> [b][c][m]
    gemm_mma<0><<<dim3(8, 12, NB), 256, SMEMSZ>>>(
        wq, xn, nullptr, qk, v, b_qkv, nullptr);
    // fused S + softmax + O -> oT
    flash_kernel<<<dim3(8, 64), 128, FSMEM>>>(qk, v, oT);
    // out = x + w_proj O + b_proj
    gemm_mma<3><<<dim3(8, 4, NB), 256, SMEMSZ>>>(
        wp, oT, out, nullptr, nullptr, b_proj, x);
}